// round 1
// baseline (speedup 1.0000x reference)
#include <cuda_runtime.h>
#include <cuda_bf16.h>
#include <math.h>

#define H    4
#define NN   4096
#define CHAN 16
#define ADIM 64
#define VDIM 16
#define D    64        // 4*CHAN
#define TJ   64        // key tile

// Scratch (device globals: no runtime allocation allowed)
__device__ float g_Q[H * NN * D];
__device__ float g_K[H * NN * D];
__device__ float g_V[H * NN * D];
__device__ float g_O[H * NN * D];

// ---------------------------------------------------------------------------
// Kernel 1: QKV projection + stacking + vec activation (Q,K only)
// grid (NN/128, H), 128 threads; thread = one token n for head h.
// ---------------------------------------------------------------------------
__device__ __forceinline__ void project_store(
    const float* __restrict__ sw_a,   // [CHAN][ADIM] in smem
    const float* __restrict__ sw_v,   // [CHAN][VDIM] in smem
    const float* __restrict__ a,      // [ADIM] regs
    const float (*__restrict__ v)[3], // [VDIM][3] regs
    float* __restrict__ dst,          // global, 64 floats
    bool actv)
{
#pragma unroll
    for (int c = 0; c < CHAN; c++) {
        float s0 = 0.f;
#pragma unroll
        for (int j = 0; j < ADIM; j++) s0 += sw_a[c * ADIM + j] * a[j];
        float s1 = 0.f, s2 = 0.f, s3 = 0.f;
#pragma unroll
        for (int j = 0; j < VDIM; j++) {
            float w = sw_v[c * VDIM + j];
            s1 += w * v[j][0];
            s2 += w * v[j][1];
            s3 += w * v[j][2];
        }
        if (actv) {
            float nsq = s0 * s0 + s1 * s1 + s2 * s2 + s3 * s3;
            float sc  = rsqrtf(sqrtf(1.0f + nsq));  // (1+nsq)^(-1/4)
            s0 *= sc; s1 *= sc; s2 *= sc; s3 *= sc;
        }
        float4 out = make_float4(s0, s1, s2, s3);
        *reinterpret_cast<float4*>(dst + 4 * c) = out;
    }
}

__global__ __launch_bounds__(128)
void proj_kernel(const float* __restrict__ ax, const float* __restrict__ vx,
                 const float* __restrict__ W_aq, const float* __restrict__ W_vq,
                 const float* __restrict__ W_ak, const float* __restrict__ W_vk,
                 const float* __restrict__ W_av, const float* __restrict__ W_vv)
{
    const int h = blockIdx.y;
    const int n = blockIdx.x * 128 + threadIdx.x;

    __shared__ float s_aq[CHAN * ADIM], s_ak[CHAN * ADIM], s_av[CHAN * ADIM];
    __shared__ float s_vq[CHAN * VDIM], s_vk[CHAN * VDIM], s_vv[CHAN * VDIM];

    for (int t = threadIdx.x; t < CHAN * ADIM; t += 128) {
        s_aq[t] = W_aq[h * CHAN * ADIM + t];
        s_ak[t] = W_ak[h * CHAN * ADIM + t];
        s_av[t] = W_av[h * CHAN * ADIM + t];
    }
    for (int t = threadIdx.x; t < CHAN * VDIM; t += 128) {
        s_vq[t] = W_vq[h * CHAN * VDIM + t];
        s_vk[t] = W_vk[h * CHAN * VDIM + t];
        s_vv[t] = W_vv[h * CHAN * VDIM + t];
    }
    __syncthreads();

    float a[ADIM];
#pragma unroll
    for (int j = 0; j < ADIM / 4; j++) {
        float4 t = reinterpret_cast<const float4*>(ax + n * ADIM)[j];
        a[4 * j + 0] = t.x; a[4 * j + 1] = t.y; a[4 * j + 2] = t.z; a[4 * j + 3] = t.w;
    }
    float v[VDIM][3];
#pragma unroll
    for (int j = 0; j < VDIM; j++) {
        v[j][0] = vx[(n * VDIM + j) * 3 + 0];
        v[j][1] = vx[(n * VDIM + j) * 3 + 1];
        v[j][2] = vx[(n * VDIM + j) * 3 + 2];
    }

    float* dq = g_Q + (h * NN + n) * D;
    float* dk = g_K + (h * NN + n) * D;
    float* dv = g_V + (h * NN + n) * D;
    project_store(s_aq, s_vq, a, v, dq, true);
    project_store(s_ak, s_vk, a, v, dk, true);
    project_store(s_av, s_vv, a, v, dv, false);
}

// ---------------------------------------------------------------------------
// Kernel 2: flash attention with proximity bias.
// grid (NN/128, H), 128 threads; thread = one query row i.
// ---------------------------------------------------------------------------
__global__ __launch_bounds__(128)
void attn_kernel(const float* __restrict__ pos_q, const float* __restrict__ pos_k)
{
    const int h = blockIdx.y;
    const int i = blockIdx.x * 128 + threadIdx.x;

    __shared__ float sK[TJ * D];
    __shared__ float sV[TJ * D];
    __shared__ float sP[TJ * 3];

    // inv of R0SQ = {1,4,16,64} for h=0..3
    const float invr = 1.0f / (float)(1 << (2 * h));

    float4 q[16];
    const float4* Qp = reinterpret_cast<const float4*>(g_Q + (h * NN + i) * D);
#pragma unroll
    for (int t = 0; t < 16; t++) q[t] = Qp[t];

    const float pqx = pos_q[(h * NN + i) * 3 + 0];
    const float pqy = pos_q[(h * NN + i) * 3 + 1];
    const float pqz = pos_q[(h * NN + i) * 3 + 2];

    float m = -INFINITY, l = 0.0f;
    float4 acc[16];
#pragma unroll
    for (int t = 0; t < 16; t++) acc[t] = make_float4(0.f, 0.f, 0.f, 0.f);

    for (int j0 = 0; j0 < NN; j0 += TJ) {
        __syncthreads();
        const float4* Kg = reinterpret_cast<const float4*>(g_K + (h * NN + j0) * D);
        const float4* Vg = reinterpret_cast<const float4*>(g_V + (h * NN + j0) * D);
        for (int t = threadIdx.x; t < TJ * D / 4; t += 128) {
            reinterpret_cast<float4*>(sK)[t] = Kg[t];
            reinterpret_cast<float4*>(sV)[t] = Vg[t];
        }
        for (int t = threadIdx.x; t < TJ * 3; t += 128)
            sP[t] = pos_k[(h * NN + j0) * 3 + t];
        __syncthreads();

#pragma unroll 4
        for (int j = 0; j < TJ; j++) {
            const float4* kj = reinterpret_cast<const float4*>(sK + j * D);
            float d0 = 0.f, d1 = 0.f, d2 = 0.f, d3 = 0.f;
#pragma unroll
            for (int t = 0; t < 16; t++) {
                float4 kk = kj[t];
                float4 qq = q[t];
                d0 += qq.x * kk.x; d1 += qq.y * kk.y;
                d2 += qq.z * kk.z; d3 += qq.w * kk.w;
            }
            float s = (d0 + d1) + (d2 + d3);
            float dx = pqx - sP[j * 3 + 0];
            float dy = pqy - sP[j * 3 + 1];
            float dz = pqz - sP[j * 3 + 2];
            s -= (dx * dx + dy * dy + dz * dz) * invr;

            if (s > m) {               // rare after warmup: rescale running state
                float sc = __expf(m - s);
                m = s;
                l *= sc;
#pragma unroll
                for (int t = 0; t < 16; t++) {
                    acc[t].x *= sc; acc[t].y *= sc; acc[t].z *= sc; acc[t].w *= sc;
                }
            }
            float p = __expf(s - m);
            l += p;
            const float4* vj = reinterpret_cast<const float4*>(sV + j * D);
#pragma unroll
            for (int t = 0; t < 16; t++) {
                float4 vv = vj[t];
                acc[t].x += p * vv.x; acc[t].y += p * vv.y;
                acc[t].z += p * vv.z; acc[t].w += p * vv.w;
            }
        }
    }

    const float inv = 1.0f / (l * 64.0f);   // 64 = sqrt(4096)
    float4* Op = reinterpret_cast<float4*>(g_O + (h * NN + i) * D);
#pragma unroll
    for (int t = 0; t < 16; t++) {
        float4 o = acc[t];
        o.x *= inv; o.y *= inv; o.z *= inv; o.w *= inv;
        Op[t] = o;
    }
}

// ---------------------------------------------------------------------------
// Kernel 3: output projection, sum over heads.
// grid (NN/128), 128 threads; thread = one token n.
//   ay = O[..., :16]              a_out[n,j]   = sum_h sum_i W_ao[h,j,i]*O[h,n,i]
//   vy = O[..., 16:].reshape(16,3) v_out[n,j,v] = sum_h sum_c W_vo[h,j,c]*O[h,n,16+3c+v]
// ---------------------------------------------------------------------------
__global__ __launch_bounds__(128)
void out_kernel(const float* __restrict__ W_ao, const float* __restrict__ W_vo,
                float* __restrict__ out)
{
    const int n = blockIdx.x * 128 + threadIdx.x;

    __shared__ float s_ao[H * ADIM * CHAN];  // 4096 floats
    __shared__ float s_vo[H * VDIM * CHAN];  // 1024 floats
    for (int t = threadIdx.x; t < H * ADIM * CHAN; t += 128) s_ao[t] = W_ao[t];
    for (int t = threadIdx.x; t < H * VDIM * CHAN; t += 128) s_vo[t] = W_vo[t];
    __syncthreads();

    float aacc[ADIM];
    float vacc[VDIM * 3];
#pragma unroll
    for (int j = 0; j < ADIM; j++) aacc[j] = 0.f;
#pragma unroll
    for (int j = 0; j < VDIM * 3; j++) vacc[j] = 0.f;

    for (int h = 0; h < H; h++) {
        const float* O = g_O + (h * NN + n) * D;
        const float* wa = s_ao + h * ADIM * CHAN;
        const float* wv = s_vo + h * VDIM * CHAN;
#pragma unroll
        for (int i = 0; i < CHAN; i++) {
            float oi = O[i];
#pragma unroll
            for (int j = 0; j < ADIM; j++) aacc[j] += wa[j * CHAN + i] * oi;
        }
#pragma unroll
        for (int c = 0; c < CHAN; c++) {
            float o0 = O[16 + 3 * c + 0];
            float o1 = O[16 + 3 * c + 1];
            float o2 = O[16 + 3 * c + 2];
#pragma unroll
            for (int j = 0; j < VDIM; j++) {
                float w = wv[j * CHAN + c];
                vacc[j * 3 + 0] += w * o0;
                vacc[j * 3 + 1] += w * o1;
                vacc[j * 3 + 2] += w * o2;
            }
        }
    }

    // a_out: [N, 64] at offset 0
#pragma unroll
    for (int j = 0; j < ADIM / 4; j++) {
        float4 t = make_float4(aacc[4 * j], aacc[4 * j + 1], aacc[4 * j + 2], aacc[4 * j + 3]);
        reinterpret_cast<float4*>(out + n * ADIM)[j] = t;
    }
    // v_out: [N, 16, 3] at offset N*64
    float* vo = out + NN * ADIM + n * VDIM * 3;
#pragma unroll
    for (int j = 0; j < VDIM * 3; j++) vo[j] = vacc[j];
}

// ---------------------------------------------------------------------------
extern "C" void kernel_launch(void* const* d_in, const int* in_sizes, int n_in,
                              void* d_out, int out_size)
{
    const float* ax    = (const float*)d_in[0];
    const float* vx    = (const float*)d_in[1];
    const float* pos_k = (const float*)d_in[2];
    const float* pos_q = (const float*)d_in[3];
    const float* W_aq  = (const float*)d_in[4];
    const float* W_vq  = (const float*)d_in[5];
    const float* W_ak  = (const float*)d_in[6];
    const float* W_vk  = (const float*)d_in[7];
    const float* W_av  = (const float*)d_in[8];
    const float* W_vv  = (const float*)d_in[9];
    const float* W_ao  = (const float*)d_in[10];
    const float* W_vo  = (const float*)d_in[11];
    float* out = (float*)d_out;

    proj_kernel<<<dim3(NN / 128, H), 128>>>(ax, vx, W_aq, W_vq, W_ak, W_vk, W_av, W_vv);
    attn_kernel<<<dim3(NN / 128, H), 128>>>(pos_q, pos_k);
    out_kernel<<<NN / 128, 128>>>(W_ao, W_vo, out);
}

// round 2
// speedup vs baseline: 1.7270x; 1.7270x over previous
#include <cuda_runtime.h>
#include <cuda_bf16.h>
#include <math.h>

#define H    4
#define NN   4096
#define CHAN 16
#define ADIM 64
#define VDIM 16
#define D    64        // 4*CHAN
#define TJ   64        // key tile
#define NSPLIT 3       // key-range splits (32*4*3 = 384 blocks ~= 1 wave @ 3 blocks/SM)

// Scratch (device globals: no runtime allocation allowed)
__device__ float g_Q[H * NN * D];
__device__ float g_K[H * NN * D];
__device__ float g_V[H * NN * D];
__device__ float g_O[H * NN * D];
__device__ float g_pm[NSPLIT * H * NN];
__device__ float g_pl[NSPLIT * H * NN];
__device__ float g_pacc[NSPLIT * H * NN * D];

// packed fp32x2 helpers (sm_103a FFMA2 — only reachable via PTX)
__device__ __forceinline__ void fma2(unsigned long long& d, unsigned long long a,
                                     unsigned long long b) {
    asm("fma.rn.f32x2 %0, %1, %2, %3;" : "=l"(d) : "l"(a), "l"(b), "l"(d));
}
__device__ __forceinline__ void mul2(unsigned long long& d, unsigned long long a,
                                     unsigned long long b) {
    asm("mul.rn.f32x2 %0, %1, %2;" : "=l"(d) : "l"(a), "l"(b));
}
__device__ __forceinline__ void add2(unsigned long long& d, unsigned long long a,
                                     unsigned long long b) {
    asm("add.rn.f32x2 %0, %1, %2;" : "=l"(d) : "l"(a), "l"(b));
}
__device__ __forceinline__ unsigned long long pack2(float lo, float hi) {
    unsigned long long r;
    asm("mov.b64 %0, {%1, %2};" : "=l"(r) : "f"(lo), "f"(hi));
    return r;
}
__device__ __forceinline__ void unpack2(float& lo, float& hi, unsigned long long v) {
    asm("mov.b64 {%0, %1}, %2;" : "=f"(lo), "=f"(hi) : "l"(v));
}

// ---------------------------------------------------------------------------
// Kernel 1: QKV projection. grid (NN/64, H, 3), 64 threads.
// blockIdx.z selects which of Q/K/V this block produces.
// ---------------------------------------------------------------------------
__global__ __launch_bounds__(64)
void proj_kernel(const float* __restrict__ ax, const float* __restrict__ vx,
                 const float* __restrict__ W_aq, const float* __restrict__ W_vq,
                 const float* __restrict__ W_ak, const float* __restrict__ W_vk,
                 const float* __restrict__ W_av, const float* __restrict__ W_vv)
{
    const int h = blockIdx.y;
    const int z = blockIdx.z;          // 0=Q 1=K 2=V
    const int n = blockIdx.x * 64 + threadIdx.x;

    const float* Wa = (z == 0) ? W_aq : (z == 1) ? W_ak : W_av;
    const float* Wv = (z == 0) ? W_vq : (z == 1) ? W_vk : W_vv;
    float* dstbase   = (z == 0) ? g_Q  : (z == 1) ? g_K  : g_V;
    const bool actv = (z < 2);

    __shared__ float s_a[CHAN * ADIM];
    __shared__ float s_v[CHAN * VDIM];
    for (int t = threadIdx.x; t < CHAN * ADIM; t += 64)
        s_a[t] = Wa[h * CHAN * ADIM + t];
    for (int t = threadIdx.x; t < CHAN * VDIM; t += 64)
        s_v[t] = Wv[h * CHAN * VDIM + t];
    __syncthreads();

    float a[ADIM];
#pragma unroll
    for (int j = 0; j < ADIM / 4; j++) {
        float4 t = reinterpret_cast<const float4*>(ax + n * ADIM)[j];
        a[4 * j + 0] = t.x; a[4 * j + 1] = t.y; a[4 * j + 2] = t.z; a[4 * j + 3] = t.w;
    }
    float v[VDIM][3];
#pragma unroll
    for (int j = 0; j < VDIM; j++) {
        v[j][0] = vx[(n * VDIM + j) * 3 + 0];
        v[j][1] = vx[(n * VDIM + j) * 3 + 1];
        v[j][2] = vx[(n * VDIM + j) * 3 + 2];
    }

    float* dst = dstbase + (h * NN + n) * D;
#pragma unroll
    for (int c = 0; c < CHAN; c++) {
        float s0 = 0.f;
#pragma unroll
        for (int j = 0; j < ADIM; j++) s0 += s_a[c * ADIM + j] * a[j];
        float s1 = 0.f, s2 = 0.f, s3 = 0.f;
#pragma unroll
        for (int j = 0; j < VDIM; j++) {
            float w = s_v[c * VDIM + j];
            s1 += w * v[j][0];
            s2 += w * v[j][1];
            s3 += w * v[j][2];
        }
        if (actv) {
            float nsq = s0 * s0 + s1 * s1 + s2 * s2 + s3 * s3;
            float sc  = rsqrtf(sqrtf(1.0f + nsq));  // (1+nsq)^(-1/4)
            s0 *= sc; s1 *= sc; s2 *= sc; s3 *= sc;
        }
        *reinterpret_cast<float4*>(dst + 4 * c) = make_float4(s0, s1, s2, s3);
    }
}

// ---------------------------------------------------------------------------
// Kernel 2: flash attention, key-range split 3 ways (partials to scratch).
// grid (NN/128, H, NSPLIT), 128 threads; thread = one query row.
// ---------------------------------------------------------------------------
__global__ __launch_bounds__(128, 3)
void attn_kernel(const float* __restrict__ pos_q, const float* __restrict__ pos_k)
{
    const int h = blockIdx.y;
    const int s = blockIdx.z;
    const int i = blockIdx.x * 128 + threadIdx.x;

    // 64 key tiles split 22/21/21
    const int t0 = (s == 0) ? 0 : (s == 1) ? 22 : 43;
    const int t1 = (s == 0) ? 22 : (s == 1) ? 43 : 64;

    __shared__ float sK[TJ * D];
    __shared__ float sV[TJ * D];
    __shared__ float sP[TJ * 3];

    const float invr = 1.0f / (float)(1 << (2 * h));   // 1/R0SQ[h]

    typedef unsigned long long u64;
    u64 q[D / 2];
    const ulonglong2* Qp = reinterpret_cast<const ulonglong2*>(g_Q + (h * NN + i) * D);
#pragma unroll
    for (int t = 0; t < 16; t++) {
        ulonglong2 v = Qp[t];
        q[2 * t] = v.x; q[2 * t + 1] = v.y;
    }

    const float pqx = pos_q[(h * NN + i) * 3 + 0];
    const float pqy = pos_q[(h * NN + i) * 3 + 1];
    const float pqz = pos_q[(h * NN + i) * 3 + 2];

    float m = -INFINITY, l = 0.0f;
    u64 acc[D / 2];
#pragma unroll
    for (int t = 0; t < D / 2; t++) acc[t] = 0ull;

    for (int tt = t0; tt < t1; tt++) {
        const int j0 = tt * TJ;
        __syncthreads();
        const float4* Kg = reinterpret_cast<const float4*>(g_K + (h * NN + j0) * D);
        const float4* Vg = reinterpret_cast<const float4*>(g_V + (h * NN + j0) * D);
        for (int t = threadIdx.x; t < TJ * D / 4; t += 128) {
            reinterpret_cast<float4*>(sK)[t] = Kg[t];
            reinterpret_cast<float4*>(sV)[t] = Vg[t];
        }
        for (int t = threadIdx.x; t < TJ * 3; t += 128)
            sP[t] = pos_k[(h * NN + j0) * 3 + t];
        __syncthreads();

#pragma unroll 2
        for (int j = 0; j < TJ; j++) {
            const ulonglong2* kj = reinterpret_cast<const ulonglong2*>(sK + j * D);
            u64 d0 = 0ull, d1 = 0ull, d2 = 0ull, d3 = 0ull;
#pragma unroll
            for (int t = 0; t < 8; t++) {
                ulonglong2 k0 = kj[2 * t];
                ulonglong2 k1 = kj[2 * t + 1];
                fma2(d0, q[4 * t + 0], k0.x);
                fma2(d1, q[4 * t + 1], k0.y);
                fma2(d2, q[4 * t + 2], k1.x);
                fma2(d3, q[4 * t + 3], k1.y);
            }
            add2(d0, d0, d1);
            add2(d2, d2, d3);
            add2(d0, d0, d2);
            float slo, shi;
            unpack2(slo, shi, d0);
            float sc = slo + shi;

            float dx = pqx - sP[j * 3 + 0];
            float dy = pqy - sP[j * 3 + 1];
            float dz = pqz - sP[j * 3 + 2];
            sc -= (dx * dx + dy * dy + dz * dz) * invr;

            if (sc > m) {                       // rare after warmup
                float r = __expf(m - sc);
                m = sc;
                l *= r;
                u64 rr = pack2(r, r);
#pragma unroll
                for (int t = 0; t < D / 2; t++) mul2(acc[t], acc[t], rr);
            }
            float p = __expf(sc - m);
            l += p;
            u64 pp = pack2(p, p);
            const ulonglong2* vj = reinterpret_cast<const ulonglong2*>(sV + j * D);
#pragma unroll
            for (int t = 0; t < 16; t++) {
                ulonglong2 vv = vj[t];
                fma2(acc[2 * t + 0], pp, vv.x);
                fma2(acc[2 * t + 1], pp, vv.y);
            }
        }
    }

    const int idx = (s * H + h) * NN + i;
    g_pm[idx] = m;
    g_pl[idx] = l;
    ulonglong2* Pp = reinterpret_cast<ulonglong2*>(g_pacc + (size_t)idx * D);
#pragma unroll
    for (int t = 0; t < 16; t++) {
        ulonglong2 o;
        o.x = acc[2 * t + 0];
        o.y = acc[2 * t + 1];
        Pp[t] = o;
    }
}

// ---------------------------------------------------------------------------
// Kernel 2b: combine split partials -> g_O. thread = one (h,i) row.
// ---------------------------------------------------------------------------
__global__ __launch_bounds__(128)
void combine_kernel()
{
    const int idx = blockIdx.x * 128 + threadIdx.x;   // h*NN + i
    const int SZ = H * NN;

    float m0 = g_pm[idx], m1 = g_pm[SZ + idx], m2 = g_pm[2 * SZ + idx];
    float M = fmaxf(m0, fmaxf(m1, m2));
    float w0 = __expf(m0 - M);
    float w1 = __expf(m1 - M);
    float w2 = __expf(m2 - M);
    float l = w0 * g_pl[idx] + w1 * g_pl[SZ + idx] + w2 * g_pl[2 * SZ + idx];
    float inv = 1.0f / (l * 64.0f);   // 64 = sqrt(4096)
    w0 *= inv; w1 *= inv; w2 *= inv;

    const float4* a0 = reinterpret_cast<const float4*>(g_pacc + (size_t)idx * D);
    const float4* a1 = reinterpret_cast<const float4*>(g_pacc + (size_t)(SZ + idx) * D);
    const float4* a2 = reinterpret_cast<const float4*>(g_pacc + (size_t)(2 * SZ + idx) * D);
    float4* Op = reinterpret_cast<float4*>(g_O + (size_t)idx * D);
#pragma unroll
    for (int t = 0; t < 16; t++) {
        float4 x0 = a0[t], x1 = a1[t], x2 = a2[t];
        float4 o;
        o.x = w0 * x0.x + w1 * x1.x + w2 * x2.x;
        o.y = w0 * x0.y + w1 * x1.y + w2 * x2.y;
        o.z = w0 * x0.z + w1 * x1.z + w2 * x2.z;
        o.w = w0 * x0.w + w1 * x1.w + w2 * x2.w;
        Op[t] = o;
    }
}

// ---------------------------------------------------------------------------
// Kernel 3: output projection, sum over heads. thread = one token n.
// ---------------------------------------------------------------------------
__global__ __launch_bounds__(64)
void out_kernel(const float* __restrict__ W_ao, const float* __restrict__ W_vo,
                float* __restrict__ out)
{
    const int n = blockIdx.x * 64 + threadIdx.x;

    __shared__ float s_ao[H * ADIM * CHAN];  // 4096 floats
    __shared__ float s_vo[H * VDIM * CHAN];  // 1024 floats
    for (int t = threadIdx.x; t < H * ADIM * CHAN; t += 64) s_ao[t] = W_ao[t];
    for (int t = threadIdx.x; t < H * VDIM * CHAN; t += 64) s_vo[t] = W_vo[t];
    __syncthreads();

    float aacc[ADIM];
    float vacc[VDIM * 3];
#pragma unroll
    for (int j = 0; j < ADIM; j++) aacc[j] = 0.f;
#pragma unroll
    for (int j = 0; j < VDIM * 3; j++) vacc[j] = 0.f;

    for (int h = 0; h < H; h++) {
        const float* O = g_O + (h * NN + n) * D;
        const float* wa = s_ao + h * ADIM * CHAN;
        const float* wv = s_vo + h * VDIM * CHAN;
#pragma unroll
        for (int i = 0; i < CHAN; i++) {
            float oi = O[i];
#pragma unroll
            for (int j = 0; j < ADIM; j++) aacc[j] += wa[j * CHAN + i] * oi;
        }
#pragma unroll
        for (int c = 0; c < CHAN; c++) {
            float o0 = O[16 + 3 * c + 0];
            float o1 = O[16 + 3 * c + 1];
            float o2 = O[16 + 3 * c + 2];
#pragma unroll
            for (int j = 0; j < VDIM; j++) {
                float w = wv[j * CHAN + c];
                vacc[j * 3 + 0] += w * o0;
                vacc[j * 3 + 1] += w * o1;
                vacc[j * 3 + 2] += w * o2;
            }
        }
    }

#pragma unroll
    for (int j = 0; j < ADIM / 4; j++)
        reinterpret_cast<float4*>(out + n * ADIM)[j] =
            make_float4(aacc[4 * j], aacc[4 * j + 1], aacc[4 * j + 2], aacc[4 * j + 3]);
    float* vo = out + NN * ADIM + n * VDIM * 3;
#pragma unroll
    for (int j = 0; j < VDIM * 3; j++) vo[j] = vacc[j];
}

// ---------------------------------------------------------------------------
extern "C" void kernel_launch(void* const* d_in, const int* in_sizes, int n_in,
                              void* d_out, int out_size)
{
    const float* ax    = (const float*)d_in[0];
    const float* vx    = (const float*)d_in[1];
    const float* pos_k = (const float*)d_in[2];
    const float* pos_q = (const float*)d_in[3];
    const float* W_aq  = (const float*)d_in[4];
    const float* W_vq  = (const float*)d_in[5];
    const float* W_ak  = (const float*)d_in[6];
    const float* W_vk  = (const float*)d_in[7];
    const float* W_av  = (const float*)d_in[8];
    const float* W_vv  = (const float*)d_in[9];
    const float* W_ao  = (const float*)d_in[10];
    const float* W_vo  = (const float*)d_in[11];
    float* out = (float*)d_out;

    proj_kernel<<<dim3(NN / 64, H, 3), 64>>>(ax, vx, W_aq, W_vq, W_ak, W_vk, W_av, W_vv);
    attn_kernel<<<dim3(NN / 128, H, NSPLIT), 128>>>(pos_q, pos_k);
    combine_kernel<<<H * NN / 128, 128>>>();
    out_kernel<<<NN / 64, 64>>>(W_ao, W_vo, out);
}

// round 4
// speedup vs baseline: 2.7745x; 1.6066x over previous
#include <cuda_runtime.h>
#include <cuda_bf16.h>
#include <cstdint>
#include <math.h>

#define H    4
#define NN   4096
#define CHAN 16
#define ADIM 64
#define VDIM 16
#define D    64
#define EXT  80          // 64 feature dims + 5 bias dims + zero pad (5 ksteps of 16)
#define QT   64          // query rows per CTA (16 per warp)
#define KT   64          // key tile

// ---------------- device global scratch (no runtime alloc allowed) ----------
__device__ __align__(16) __nv_bfloat16 g_Qe[2][H][NN][EXT];   // hi/lo split
__device__ __align__(16) __nv_bfloat16 g_Ke[2][H][NN][EXT];
__device__ __align__(16) float         g_V [H][NN][D];
__device__ __align__(16) __nv_bfloat16 g_Vt[2][H][D][NN];     // transposed, hi/lo
__device__ __align__(16) float         g_O [H][NN][D];

// ---------------- warp-MMA helpers -----------------------------------------
__device__ __forceinline__ uint32_t smem_u32(const void* p) {
    uint32_t a;
    asm("{ .reg .u64 t; cvta.to.shared.u64 t, %1; cvt.u32.u64 %0, t; }" : "=r"(a) : "l"(p));
    return a;
}
__device__ __forceinline__ void ldm_x4(uint32_t* r, uint32_t addr) {
    asm volatile("ldmatrix.sync.aligned.m8n8.x4.shared.b16 {%0,%1,%2,%3}, [%4];"
                 : "=r"(r[0]), "=r"(r[1]), "=r"(r[2]), "=r"(r[3]) : "r"(addr));
}
__device__ __forceinline__ void ldm_x2(uint32_t& b0, uint32_t& b1, uint32_t addr) {
    asm volatile("ldmatrix.sync.aligned.m8n8.x2.shared.b16 {%0,%1}, [%2];"
                 : "=r"(b0), "=r"(b1) : "r"(addr));
}
__device__ __forceinline__ void mma16816(float* c, const uint32_t* a,
                                         uint32_t b0, uint32_t b1) {
    asm volatile("mma.sync.aligned.m16n8k16.row.col.f32.bf16.bf16.f32 "
                 "{%0,%1,%2,%3}, {%4,%5,%6,%7}, {%8,%9}, {%0,%1,%2,%3};"
                 : "+f"(c[0]), "+f"(c[1]), "+f"(c[2]), "+f"(c[3])
                 : "r"(a[0]), "r"(a[1]), "r"(a[2]), "r"(a[3]), "r"(b0), "r"(b1));
}
// pack two f32 into bf16x2 (x0 -> low half) and residual bf16x2
__device__ __forceinline__ void pack_hilo(float x0, float x1, uint32_t& hi, uint32_t& lo) {
    asm("cvt.rn.bf16x2.f32 %0, %1, %2;" : "=r"(hi) : "f"(x1), "f"(x0));
    float f0 = __uint_as_float(hi << 16);
    float f1 = __uint_as_float(hi & 0xffff0000u);
    asm("cvt.rn.bf16x2.f32 %0, %1, %2;" : "=r"(lo) : "f"(x1 - f1), "f"(x0 - f0));
}

// padded smem row strides (16B-granule shifted -> conflict-free ldmatrix)
#define KSTRIDE 176      // 160B data + 16B pad
#define VSTRIDE 144      // 128B data + 16B pad

// ---------------------------------------------------------------------------
// Kernel 1: projection -> Qext/Kext (bf16 hi/lo) and V (fp32)
// grid (NN/64, H, 3), 64 threads
// ---------------------------------------------------------------------------
__global__ __launch_bounds__(64)
void proj_kernel(const float* __restrict__ ax, const float* __restrict__ vx,
                 const float* __restrict__ pos_q, const float* __restrict__ pos_k,
                 const float* __restrict__ W_aq, const float* __restrict__ W_vq,
                 const float* __restrict__ W_ak, const float* __restrict__ W_vk,
                 const float* __restrict__ W_av, const float* __restrict__ W_vv)
{
    const int h = blockIdx.y;
    const int z = blockIdx.z;          // 0=Q 1=K 2=V
    const int n = blockIdx.x * 64 + threadIdx.x;

    const float* Wa = (z == 0) ? W_aq : (z == 1) ? W_ak : W_av;
    const float* Wv = (z == 0) ? W_vq : (z == 1) ? W_vk : W_vv;

    __shared__ float s_a[CHAN * ADIM];
    __shared__ float s_v[CHAN * VDIM];
    for (int t = threadIdx.x; t < CHAN * ADIM; t += 64) s_a[t] = Wa[h * CHAN * ADIM + t];
    for (int t = threadIdx.x; t < CHAN * VDIM; t += 64) s_v[t] = Wv[h * CHAN * VDIM + t];
    __syncthreads();

    float a[ADIM];
#pragma unroll
    for (int j = 0; j < ADIM / 4; j++) {
        float4 t = reinterpret_cast<const float4*>(ax + n * ADIM)[j];
        a[4*j] = t.x; a[4*j+1] = t.y; a[4*j+2] = t.z; a[4*j+3] = t.w;
    }
    float v[VDIM][3];
#pragma unroll
    for (int j = 0; j < VDIM; j++) {
        v[j][0] = vx[(n * VDIM + j) * 3 + 0];
        v[j][1] = vx[(n * VDIM + j) * 3 + 1];
        v[j][2] = vx[(n * VDIM + j) * 3 + 2];
    }

    float e[EXT];
#pragma unroll
    for (int c = 0; c < CHAN; c++) {
        float s0 = 0.f;
#pragma unroll
        for (int j = 0; j < ADIM; j++) s0 += s_a[c * ADIM + j] * a[j];
        float s1 = 0.f, s2 = 0.f, s3 = 0.f;
#pragma unroll
        for (int j = 0; j < VDIM; j++) {
            float w = s_v[c * VDIM + j];
            s1 += w * v[j][0]; s2 += w * v[j][1]; s3 += w * v[j][2];
        }
        if (z < 2) {
            float nsq = s0*s0 + s1*s1 + s2*s2 + s3*s3;
            float sc  = rsqrtf(sqrtf(1.0f + nsq));
            s0 *= sc; s1 *= sc; s2 *= sc; s3 *= sc;
        }
        e[4*c] = s0; e[4*c+1] = s1; e[4*c+2] = s2; e[4*c+3] = s3;
    }

    if (z == 2) {   // V: plain fp32
#pragma unroll
        for (int j = 0; j < D / 4; j++)
            reinterpret_cast<float4*>(&g_V[h][n][0])[j] =
                make_float4(e[4*j], e[4*j+1], e[4*j+2], e[4*j+3]);
        return;
    }

    // bias extension dims
    const float invr = 1.0f / (float)(1 << (2 * h));
#pragma unroll
    for (int j = D; j < EXT; j++) e[j] = 0.f;
    if (z == 0) {   // Q side: [2*invr*pq, -invr, -invr]
        const float* pq = pos_q + (h * NN + n) * 3;
        e[64] = 2.f * invr * pq[0];
        e[65] = 2.f * invr * pq[1];
        e[66] = 2.f * invr * pq[2];
        e[67] = -invr;   // exact bf16 (power of 2)
        e[68] = -invr;
    } else {        // K side: [pk, split(|pk|^2)]
        const float* pk = pos_k + (h * NN + n) * 3;
        e[64] = pk[0]; e[65] = pk[1]; e[66] = pk[2];
        float w = pk[0]*pk[0] + pk[1]*pk[1] + pk[2]*pk[2];
        float whi = __bfloat162float(__float2bfloat16(w));
        e[67] = whi;
        e[68] = w - whi;
    }

    __nv_bfloat16* dhi = (z == 0) ? &g_Qe[0][h][n][0] : &g_Ke[0][h][n][0];
    __nv_bfloat16* dlo = (z == 0) ? &g_Qe[1][h][n][0] : &g_Ke[1][h][n][0];
#pragma unroll
    for (int j = 0; j < EXT; j++) {
        __nv_bfloat16 hi = __float2bfloat16(e[j]);
        dhi[j] = hi;
        dlo[j] = __float2bfloat16(e[j] - __bfloat162float(hi));
    }
}

// ---------------------------------------------------------------------------
// Kernel 1b: V transpose -> g_Vt hi/lo. grid (NN/64, H), 256 threads.
// ---------------------------------------------------------------------------
__global__ __launch_bounds__(256)
void vtrans_kernel()
{
    const int h  = blockIdx.y;
    const int n0 = blockIdx.x * 64;
    __shared__ float ts[64][65];
    for (int u = threadIdx.x; u < 64 * 64; u += 256) {
        int nl = u >> 6, d = u & 63;
        ts[nl][d] = g_V[h][n0 + nl][d];
    }
    __syncthreads();
    for (int u = threadIdx.x; u < 64 * 64; u += 256) {
        int d = u >> 6, nl = u & 63;
        float x = ts[nl][d];
        __nv_bfloat16 hi = __float2bfloat16(x);
        g_Vt[0][h][d][n0 + nl] = hi;
        g_Vt[1][h][d][n0 + nl] = __float2bfloat16(x - __bfloat162float(hi));
    }
}

// ---------------------------------------------------------------------------
// Kernel 2: HMMA flash attention. grid (NN/QT, H), 128 threads (4 warps).
// Warp w owns query rows q0 + 16w .. 16w+15.
// ---------------------------------------------------------------------------
__global__ __launch_bounds__(128)
void attn_kernel()
{
    __shared__ __align__(16) uint8_t sK[2][64 * KSTRIDE];   // K tile hi/lo (Q staged here first)
    __shared__ __align__(16) uint8_t sV[2][64 * VSTRIDE];   // V^T tile hi/lo

    const int tid  = threadIdx.x;
    const int wid  = tid >> 5;
    const int lane = tid & 31;
    const int h    = blockIdx.y;
    const int q0   = blockIdx.x * QT;

    const uint32_t k0a = smem_u32(&sK[0][0]);
    const uint32_t k1a = smem_u32(&sK[1][0]);
    const uint32_t v0a = smem_u32(&sV[0][0]);
    const uint32_t v1a = smem_u32(&sV[1][0]);

    // ---- stage Q tile (into sK area), then pull A-frags to registers ----
    for (int u = tid; u < 64 * 10; u += 128) {
        int row = u / 10, w = u - row * 10;
        uint32_t off = row * KSTRIDE + w * 16;
        *(uint4*)(&sK[0][off]) = ((const uint4*)&g_Qe[0][h][q0 + row][0])[w];
        *(uint4*)(&sK[1][off]) = ((const uint4*)&g_Qe[1][h][q0 + row][0])[w];
    }
    __syncthreads();

    uint32_t qh[5][4], ql[5][4];
    {
        uint32_t qoff = (wid * 16 + (lane & 15)) * KSTRIDE + (lane >> 4) * 16;
#pragma unroll
        for (int ks = 0; ks < 5; ks++) {
            ldm_x4(qh[ks], k0a + qoff + ks * 32);
            ldm_x4(ql[ks], k1a + qoff + ks * 32);
        }
    }

    // per-thread per-row stats (rows: lane/4 and lane/4+8 within warp's 16)
    float m0 = -INFINITY, m1 = -INFINITY, l0 = 0.f, l1 = 0.f;
    float o[8][4];
#pragma unroll
    for (int g = 0; g < 8; g++) { o[g][0]=0.f; o[g][1]=0.f; o[g][2]=0.f; o[g][3]=0.f; }

    // precomputed ldmatrix base offsets
    const uint32_t kbo = (lane & 7) * KSTRIDE + ((lane >> 3) & 1) * 16;
    const uint32_t vbo = (lane & 7) * VSTRIDE + ((lane >> 3) & 1) * 16;

    for (int t = 0; t < NN / KT; t++) {
        const int j0 = t * KT;
        __syncthreads();   // everyone done reading previous tile
        for (int u = tid; u < 64 * 10; u += 128) {
            int row = u / 10, w = u - row * 10;
            uint32_t off = row * KSTRIDE + w * 16;
            *(uint4*)(&sK[0][off]) = ((const uint4*)&g_Ke[0][h][j0 + row][0])[w];
            *(uint4*)(&sK[1][off]) = ((const uint4*)&g_Ke[1][h][j0 + row][0])[w];
        }
        for (int u = tid; u < 64 * 8; u += 128) {
            int row = u >> 3, w = u & 7;
            uint32_t off = row * VSTRIDE + w * 16;
            *(uint4*)(&sV[0][off]) = ((const uint4*)&g_Vt[0][h][row][j0])[w];
            *(uint4*)(&sV[1][off]) = ((const uint4*)&g_Vt[1][h][row][j0])[w];
        }
        __syncthreads();

        // ---- S = Qext @ Kext^T : frags c[g] cover cols 8g..8g+7 ----
        float c[8][4];
#pragma unroll
        for (int g = 0; g < 8; g++) { c[g][0]=0.f; c[g][1]=0.f; c[g][2]=0.f; c[g][3]=0.f; }
#pragma unroll
        for (int g = 0; g < 8; g++) {
            uint32_t base = kbo + g * 8 * KSTRIDE;
#pragma unroll
            for (int ks = 0; ks < 5; ks++) {
                uint32_t bh0, bh1, bl0, bl1;
                ldm_x2(bh0, bh1, k0a + base + ks * 32);
                ldm_x2(bl0, bl1, k1a + base + ks * 32);
                mma16816(c[g], qh[ks], bh0, bh1);
                mma16816(c[g], ql[ks], bh0, bh1);
                mma16816(c[g], qh[ks], bl0, bl1);
                mma16816(c[g], ql[ks], bl0, bl1);
            }
        }

        // ---- online softmax (rows spread over quads) ----
        float r0 = -INFINITY, r1 = -INFINITY;
#pragma unroll
        for (int g = 0; g < 8; g++) {
            r0 = fmaxf(r0, fmaxf(c[g][0], c[g][1]));
            r1 = fmaxf(r1, fmaxf(c[g][2], c[g][3]));
        }
        r0 = fmaxf(r0, __shfl_xor_sync(0xffffffffu, r0, 1));
        r0 = fmaxf(r0, __shfl_xor_sync(0xffffffffu, r0, 2));
        r1 = fmaxf(r1, __shfl_xor_sync(0xffffffffu, r1, 1));
        r1 = fmaxf(r1, __shfl_xor_sync(0xffffffffu, r1, 2));

        float mn0 = fmaxf(m0, r0), mn1 = fmaxf(m1, r1);
        float sc0 = __expf(m0 - mn0), sc1 = __expf(m1 - mn1);
        m0 = mn0; m1 = mn1;

        float ls0 = 0.f, ls1 = 0.f;
#pragma unroll
        for (int g = 0; g < 8; g++) {
            c[g][0] = __expf(c[g][0] - m0);
            c[g][1] = __expf(c[g][1] - m0);
            c[g][2] = __expf(c[g][2] - m1);
            c[g][3] = __expf(c[g][3] - m1);
            ls0 += c[g][0] + c[g][1];
            ls1 += c[g][2] + c[g][3];
            o[g][0] *= sc0; o[g][1] *= sc0;
            o[g][2] *= sc1; o[g][3] *= sc1;
        }
        l0 = l0 * sc0 + ls0;
        l1 = l1 * sc1 + ls1;

        // ---- P -> bf16 hi/lo A-frags (kstep kk from S groups 2kk, 2kk+1) ----
        uint32_t ph[4][4], pl[4][4];
#pragma unroll
        for (int kk = 0; kk < 4; kk++) {
            pack_hilo(c[2*kk][0],   c[2*kk][1],   ph[kk][0], pl[kk][0]);
            pack_hilo(c[2*kk][2],   c[2*kk][3],   ph[kk][1], pl[kk][1]);
            pack_hilo(c[2*kk+1][0], c[2*kk+1][1], ph[kk][2], pl[kk][2]);
            pack_hilo(c[2*kk+1][2], c[2*kk+1][3], ph[kk][3], pl[kk][3]);
        }

        // ---- O += P @ V^T : o[g] covers dims 8g..8g+7 ----
#pragma unroll
        for (int g = 0; g < 8; g++) {
            uint32_t base = vbo + g * 8 * VSTRIDE;
#pragma unroll
            for (int kk = 0; kk < 4; kk++) {
                uint32_t vh0, vh1, vl0, vl1;
                ldm_x2(vh0, vh1, v0a + base + kk * 32);
                ldm_x2(vl0, vl1, v1a + base + kk * 32);
                mma16816(o[g], ph[kk], vh0, vh1);
                mma16816(o[g], pl[kk], vh0, vh1);
                mma16816(o[g], ph[kk], vl0, vl1);
            }
        }
    }

    // ---- epilogue ----
    l0 += __shfl_xor_sync(0xffffffffu, l0, 1);
    l0 += __shfl_xor_sync(0xffffffffu, l0, 2);
    l1 += __shfl_xor_sync(0xffffffffu, l1, 1);
    l1 += __shfl_xor_sync(0xffffffffu, l1, 2);
    const float inv0 = 1.0f / (l0 * 64.0f);   // 64 = sqrt(4096)
    const float inv1 = 1.0f / (l1 * 64.0f);

    const int r0row = q0 + wid * 16 + (lane >> 2);
    const int r1row = r0row + 8;
    const int dcol  = 2 * (lane & 3);
#pragma unroll
    for (int g = 0; g < 8; g++) {
        int d = 8 * g + dcol;
        *reinterpret_cast<float2*>(&g_O[h][r0row][d]) = make_float2(o[g][0]*inv0, o[g][1]*inv0);
        *reinterpret_cast<float2*>(&g_O[h][r1row][d]) = make_float2(o[g][2]*inv1, o[g][3]*inv1);
    }
}

// ---------------------------------------------------------------------------
// Kernel 3: output projection. grid (NN/64, 2), 64 threads.
// ---------------------------------------------------------------------------
__global__ __launch_bounds__(64)
void out_kernel(const float* __restrict__ W_ao, const float* __restrict__ W_vo,
                float* __restrict__ out)
{
    const int n = blockIdx.x * 64 + threadIdx.x;
    const int z = blockIdx.y;

    if (z == 0) {
        __shared__ float s_ao[H * ADIM * CHAN];
        for (int t = threadIdx.x; t < H * ADIM * CHAN; t += 64) s_ao[t] = W_ao[t];
        __syncthreads();
        float acc[ADIM];
#pragma unroll
        for (int j = 0; j < ADIM; j++) acc[j] = 0.f;
        for (int h = 0; h < H; h++) {
            const float* O = &g_O[h][n][0];
            const float* w = s_ao + h * ADIM * CHAN;
#pragma unroll
            for (int i = 0; i < CHAN; i++) {
                float oi = O[i];
#pragma unroll
                for (int j = 0; j < ADIM; j++) acc[j] += w[j * CHAN + i] * oi;
            }
        }
#pragma unroll
        for (int j = 0; j < ADIM / 4; j++)
            reinterpret_cast<float4*>(out + n * ADIM)[j] =
                make_float4(acc[4*j], acc[4*j+1], acc[4*j+2], acc[4*j+3]);
    } else {
        __shared__ float s_vo[H * VDIM * CHAN];
        for (int t = threadIdx.x; t < H * VDIM * CHAN; t += 64) s_vo[t] = W_vo[t];
        __syncthreads();
        float acc[VDIM * 3];
#pragma unroll
        for (int j = 0; j < VDIM * 3; j++) acc[j] = 0.f;
        for (int h = 0; h < H; h++) {
            const float* O = &g_O[h][n][0];
            const float* w = s_vo + h * VDIM * CHAN;
#pragma unroll
            for (int c = 0; c < CHAN; c++) {
                float o0 = O[16 + 3*c], o1 = O[17 + 3*c], o2 = O[18 + 3*c];
#pragma unroll
                for (int j = 0; j < VDIM; j++) {
                    float ww = w[j * CHAN + c];
                    acc[j*3]   += ww * o0;
                    acc[j*3+1] += ww * o1;
                    acc[j*3+2] += ww * o2;
                }
            }
        }
        float* vo = out + NN * ADIM + n * VDIM * 3;
#pragma unroll
        for (int j = 0; j < VDIM * 3; j++) vo[j] = acc[j];
    }
}

// ---------------------------------------------------------------------------
extern "C" void kernel_launch(void* const* d_in, const int* in_sizes, int n_in,
                              void* d_out, int out_size)
{
    const float* ax    = (const float*)d_in[0];
    const float* vx    = (const float*)d_in[1];
    const float* pos_k = (const float*)d_in[2];
    const float* pos_q = (const float*)d_in[3];
    const float* W_aq  = (const float*)d_in[4];
    const float* W_vq  = (const float*)d_in[5];
    const float* W_ak  = (const float*)d_in[6];
    const float* W_vk  = (const float*)d_in[7];
    const float* W_av  = (const float*)d_in[8];
    const float* W_vv  = (const float*)d_in[9];
    const float* W_ao  = (const float*)d_in[10];
    const float* W_vo  = (const float*)d_in[11];
    float* out = (float*)d_out;

    proj_kernel<<<dim3(NN / 64, H, 3), 64>>>(ax, vx, pos_q, pos_k,
                                             W_aq, W_vq, W_ak, W_vk, W_av, W_vv);
    vtrans_kernel<<<dim3(NN / 64, H), 256>>>();
    attn_kernel<<<dim3(NN / QT, H), 128>>>();
    out_kernel<<<dim3(NN / 64, 2), 64>>>(W_ao, W_vo, out);
}

// round 5
// speedup vs baseline: 3.7218x; 1.3415x over previous
#include <cuda_runtime.h>
#include <cuda_bf16.h>
#include <cstdint>
#include <math.h>

#define H    4
#define NN   4096
#define CHAN 16
#define ADIM 64
#define VDIM 16
#define D    64
#define EXT  80          // 64 feature dims + 5 bias dims + zero pad (5 ksteps of 16)
#define QT   64          // query rows per CTA (16 per warp)
#define KT   64          // key tile
#define NT   (NN / KT)   // 64 key tiles

#define LOG2E 1.4426950408889634f

// ---------------- device global scratch (no runtime alloc allowed) ----------
__device__ __align__(16) __nv_bfloat16 g_Qe[2][H][NN][EXT];   // hi/lo split (Q pre-scaled by log2e)
__device__ __align__(16) __nv_bfloat16 g_Ke[2][H][NN][EXT];
__device__ __align__(16) float         g_V [H][NN][D];
__device__ __align__(16) __nv_bfloat16 g_Vt[2][H][D][NN];     // transposed, hi/lo
__device__ __align__(16) float         g_O [H][NN][D];

// ---------------- helpers ---------------------------------------------------
__device__ __forceinline__ uint32_t smem_u32(const void* p) {
    uint32_t a;
    asm("{ .reg .u64 t; cvta.to.shared.u64 t, %1; cvt.u32.u64 %0, t; }" : "=r"(a) : "l"(p));
    return a;
}
__device__ __forceinline__ void ldm_x4(uint32_t* r, uint32_t addr) {
    asm volatile("ldmatrix.sync.aligned.m8n8.x4.shared.b16 {%0,%1,%2,%3}, [%4];"
                 : "=r"(r[0]), "=r"(r[1]), "=r"(r[2]), "=r"(r[3]) : "r"(addr));
}
__device__ __forceinline__ void mma16816(float* c, const uint32_t* a,
                                         uint32_t b0, uint32_t b1) {
    asm volatile("mma.sync.aligned.m16n8k16.row.col.f32.bf16.bf16.f32 "
                 "{%0,%1,%2,%3}, {%4,%5,%6,%7}, {%8,%9}, {%0,%1,%2,%3};"
                 : "+f"(c[0]), "+f"(c[1]), "+f"(c[2]), "+f"(c[3])
                 : "r"(a[0]), "r"(a[1]), "r"(a[2]), "r"(a[3]), "r"(b0), "r"(b1));
}
__device__ __forceinline__ void pack_hilo(float x0, float x1, uint32_t& hi, uint32_t& lo) {
    asm("cvt.rn.bf16x2.f32 %0, %1, %2;" : "=r"(hi) : "f"(x1), "f"(x0));
    float f0 = __uint_as_float(hi << 16);
    float f1 = __uint_as_float(hi & 0xffff0000u);
    asm("cvt.rn.bf16x2.f32 %0, %1, %2;" : "=r"(lo) : "f"(x1 - f1), "f"(x0 - f0));
}
__device__ __forceinline__ float ex2(float x) {
    float y;
    asm("ex2.approx.f32 %0, %1;" : "=f"(y) : "f"(x));
    return y;
}
__device__ __forceinline__ void cp16(uint32_t saddr, const void* gaddr) {
    asm volatile("cp.async.ca.shared.global [%0], [%1], 16;" :: "r"(saddr), "l"(gaddr) : "memory");
}
#define CP_COMMIT() asm volatile("cp.async.commit_group;" ::: "memory")
#define CP_WAIT1()  asm volatile("cp.async.wait_group 1;"  ::: "memory")
#define CP_WAIT0()  asm volatile("cp.async.wait_group 0;"  ::: "memory")

// padded smem row strides (conflict-free ldmatrix)
#define KSTRIDE 176      // 160B data + 16B pad
#define VSTRIDE 144      // 128B data + 16B pad
#define KB_HL   (64 * KSTRIDE)                 // 11264 per hi/lo plane
#define VB_HL   (64 * VSTRIDE)                 // 9216
#define STAGE_BYTES (2 * KB_HL + 2 * VB_HL)    // 40960
#define SMEM_BYTES  (2 * STAGE_BYTES)          // 81920

// ---------------------------------------------------------------------------
// Kernel 1: projection -> Qext/Kext (bf16 hi/lo) and V (fp32)
// grid (NN/64, H, 3), 64 threads.  Q side pre-scaled by log2e.
// ---------------------------------------------------------------------------
__global__ __launch_bounds__(64)
void proj_kernel(const float* __restrict__ ax, const float* __restrict__ vx,
                 const float* __restrict__ pos_q, const float* __restrict__ pos_k,
                 const float* __restrict__ W_aq, const float* __restrict__ W_vq,
                 const float* __restrict__ W_ak, const float* __restrict__ W_vk,
                 const float* __restrict__ W_av, const float* __restrict__ W_vv)
{
    const int h = blockIdx.y;
    const int z = blockIdx.z;          // 0=Q 1=K 2=V
    const int n = blockIdx.x * 64 + threadIdx.x;

    const float* Wa = (z == 0) ? W_aq : (z == 1) ? W_ak : W_av;
    const float* Wv = (z == 0) ? W_vq : (z == 1) ? W_vk : W_vv;

    __shared__ float s_a[CHAN * ADIM];
    __shared__ float s_v[CHAN * VDIM];
    for (int t = threadIdx.x; t < CHAN * ADIM; t += 64) s_a[t] = Wa[h * CHAN * ADIM + t];
    for (int t = threadIdx.x; t < CHAN * VDIM; t += 64) s_v[t] = Wv[h * CHAN * VDIM + t];
    __syncthreads();

    float a[ADIM];
#pragma unroll
    for (int j = 0; j < ADIM / 4; j++) {
        float4 t = reinterpret_cast<const float4*>(ax + n * ADIM)[j];
        a[4*j] = t.x; a[4*j+1] = t.y; a[4*j+2] = t.z; a[4*j+3] = t.w;
    }
    float v[VDIM][3];
#pragma unroll
    for (int j = 0; j < VDIM; j++) {
        v[j][0] = vx[(n * VDIM + j) * 3 + 0];
        v[j][1] = vx[(n * VDIM + j) * 3 + 1];
        v[j][2] = vx[(n * VDIM + j) * 3 + 2];
    }

    float e[EXT];
#pragma unroll
    for (int c = 0; c < CHAN; c++) {
        float s0 = 0.f;
#pragma unroll
        for (int j = 0; j < ADIM; j++) s0 += s_a[c * ADIM + j] * a[j];
        float s1 = 0.f, s2 = 0.f, s3 = 0.f;
#pragma unroll
        for (int j = 0; j < VDIM; j++) {
            float w = s_v[c * VDIM + j];
            s1 += w * v[j][0]; s2 += w * v[j][1]; s3 += w * v[j][2];
        }
        if (z < 2) {
            float nsq = s0*s0 + s1*s1 + s2*s2 + s3*s3;
            float sc  = rsqrtf(sqrtf(1.0f + nsq));
            s0 *= sc; s1 *= sc; s2 *= sc; s3 *= sc;
        }
        e[4*c] = s0; e[4*c+1] = s1; e[4*c+2] = s2; e[4*c+3] = s3;
    }

    if (z == 2) {   // V: plain fp32
#pragma unroll
        for (int j = 0; j < D / 4; j++)
            reinterpret_cast<float4*>(&g_V[h][n][0])[j] =
                make_float4(e[4*j], e[4*j+1], e[4*j+2], e[4*j+3]);
        return;
    }

    // bias extension dims
    const float invr = 1.0f / (float)(1 << (2 * h));
#pragma unroll
    for (int j = D; j < EXT; j++) e[j] = 0.f;
    if (z == 0) {   // Q side: [2*invr*pq, -invr, -invr], then scale everything by log2e
        const float* pq = pos_q + (h * NN + n) * 3;
        e[64] = 2.f * invr * pq[0];
        e[65] = 2.f * invr * pq[1];
        e[66] = 2.f * invr * pq[2];
        e[67] = -invr;
        e[68] = -invr;
#pragma unroll
        for (int j = 0; j < EXT; j++) e[j] *= LOG2E;
    } else {        // K side: [pk, split(|pk|^2)]
        const float* pk = pos_k + (h * NN + n) * 3;
        e[64] = pk[0]; e[65] = pk[1]; e[66] = pk[2];
        float w = pk[0]*pk[0] + pk[1]*pk[1] + pk[2]*pk[2];
        float whi = __bfloat162float(__float2bfloat16(w));
        e[67] = whi;
        e[68] = w - whi;
    }

    __nv_bfloat16* dhi = (z == 0) ? &g_Qe[0][h][n][0] : &g_Ke[0][h][n][0];
    __nv_bfloat16* dlo = (z == 0) ? &g_Qe[1][h][n][0] : &g_Ke[1][h][n][0];
#pragma unroll
    for (int j = 0; j < EXT; j++) {
        __nv_bfloat16 hi = __float2bfloat16(e[j]);
        dhi[j] = hi;
        dlo[j] = __float2bfloat16(e[j] - __bfloat162float(hi));
    }
}

// ---------------------------------------------------------------------------
// Kernel 1b: V transpose -> g_Vt hi/lo. grid (NN/64, H), 256 threads.
// ---------------------------------------------------------------------------
__global__ __launch_bounds__(256)
void vtrans_kernel()
{
    const int h  = blockIdx.y;
    const int n0 = blockIdx.x * 64;
    __shared__ float ts[64][65];
    for (int u = threadIdx.x; u < 64 * 64; u += 256) {
        int nl = u >> 6, d = u & 63;
        ts[nl][d] = g_V[h][n0 + nl][d];
    }
    __syncthreads();
    for (int u = threadIdx.x; u < 64 * 64; u += 256) {
        int d = u >> 6, nl = u & 63;
        float x = ts[nl][d];
        __nv_bfloat16 hi = __float2bfloat16(x);
        g_Vt[0][h][d][n0 + nl] = hi;
        g_Vt[1][h][d][n0 + nl] = __float2bfloat16(x - __bfloat162float(hi));
    }
}

// ---------------------------------------------------------------------------
// Kernel 2: HMMA flash attention, cp.async double-buffered.
// grid (NN/QT, H), 128 threads (4 warps), warp w owns rows q0+16w..16w+15.
// Dynamic smem: 2 stages x { Khi, Klo (64x176B), Vhi, Vlo (64x144B) }.
// ---------------------------------------------------------------------------
__global__ __launch_bounds__(128)
void attn_kernel()
{
    extern __shared__ __align__(16) uint8_t smem[];

    const int tid  = threadIdx.x;
    const int wid  = tid >> 5;
    const int lane = tid & 31;
    const int h    = blockIdx.y;
    const int q0   = blockIdx.x * QT;

    const uint32_t sbase = smem_u32(smem);

    // ---- stage Q tile into stage-0 K buffers, pull A-frags ----
    for (int u = tid; u < 64 * 10; u += 128) {
        int row = u / 10, w = u - row * 10;
        uint32_t off = row * KSTRIDE + w * 16;
        *(uint4*)(smem + off)         = ((const uint4*)&g_Qe[0][h][q0 + row][0])[w];
        *(uint4*)(smem + KB_HL + off) = ((const uint4*)&g_Qe[1][h][q0 + row][0])[w];
    }
    __syncthreads();

    uint32_t qh[5][4], ql[5][4];
    {
        uint32_t qoff = (wid * 16 + (lane & 15)) * KSTRIDE + (lane >> 4) * 16;
#pragma unroll
        for (int ks = 0; ks < 5; ks++) {
            ldm_x4(qh[ks], sbase + qoff + ks * 32);
            ldm_x4(ql[ks], sbase + KB_HL + qoff + ks * 32);
        }
    }
    __syncthreads();   // Q reads done before prefetch overwrites stage 0

    // per-lane ldmatrix base addresses for each stage (B-frags, hi/lo fused x4)
    const int hl = (lane >> 4) & 1;     // lanes 0-15 -> hi plane, 16-31 -> lo plane
    uint32_t kb[2], vb[2];
#pragma unroll
    for (int s = 0; s < 2; s++) {
        kb[s] = sbase + s * STAGE_BYTES + (hl ? KB_HL : 0)
              + (lane & 7) * KSTRIDE + ((lane >> 3) & 1) * 16;
        vb[s] = sbase + s * STAGE_BYTES + 2 * KB_HL + (hl ? VB_HL : 0)
              + (lane & 7) * VSTRIDE + ((lane >> 3) & 1) * 16;
    }

    // prefetch helper (macro-ish lambda)
    auto prefetch = [&](int t, int s) {
        const int j0 = t * KT;
        const uint32_t kB = sbase + s * STAGE_BYTES;
        for (int u = tid; u < 64 * 10; u += 128) {
            int row = u / 10, w = u - row * 10;
            uint32_t off = kB + row * KSTRIDE + w * 16;
            cp16(off,          &g_Ke[0][h][j0 + row][w * 8]);
            cp16(off + KB_HL,  &g_Ke[1][h][j0 + row][w * 8]);
        }
        const uint32_t vB = kB + 2 * KB_HL;
        for (int u = tid; u < 64 * 8; u += 128) {
            int row = u >> 3, w = u & 7;
            uint32_t off = vB + row * VSTRIDE + w * 16;
            cp16(off,          &g_Vt[0][h][row][j0 + w * 8]);
            cp16(off + VB_HL,  &g_Vt[1][h][row][j0 + w * 8]);
        }
    };

    float m0 = -INFINITY, m1 = -INFINITY, l0 = 0.f, l1 = 0.f;
    float o[8][4];
#pragma unroll
    for (int g = 0; g < 8; g++) { o[g][0]=0.f; o[g][1]=0.f; o[g][2]=0.f; o[g][3]=0.f; }

    prefetch(0, 0);
    CP_COMMIT();

    for (int t = 0; t < NT; t++) {
        const int cur = t & 1;
        if (t + 1 < NT) {
            prefetch(t + 1, cur ^ 1);
            CP_COMMIT();
            CP_WAIT1();
        } else {
            CP_WAIT0();
        }
        __syncthreads();   // stage `cur` fully resident for all warps

        // ---- S = Qext @ Kext^T : c[g] covers cols 8g..8g+7 (3 split terms) ----
        float c[8][4];
#pragma unroll
        for (int g = 0; g < 8; g++) { c[g][0]=0.f; c[g][1]=0.f; c[g][2]=0.f; c[g][3]=0.f; }
#pragma unroll
        for (int g = 0; g < 8; g++) {
            uint32_t base = kb[cur] + g * 8 * KSTRIDE;
#pragma unroll
            for (int ks = 0; ks < 5; ks++) {
                uint32_t b[4];                 // bh0,bh1 (lanes<16) | bl0,bl1 (lanes>=16)
                ldm_x4(b, base + ks * 32);
                mma16816(c[g], qh[ks], b[0], b[1]);
                mma16816(c[g], ql[ks], b[0], b[1]);
                mma16816(c[g], qh[ks], b[2], b[3]);
            }
        }

        // ---- online softmax in log2 domain (Q pre-scaled by log2e) ----
        float r0 = -INFINITY, r1 = -INFINITY;
#pragma unroll
        for (int g = 0; g < 8; g++) {
            r0 = fmaxf(r0, fmaxf(c[g][0], c[g][1]));
            r1 = fmaxf(r1, fmaxf(c[g][2], c[g][3]));
        }
        r0 = fmaxf(r0, __shfl_xor_sync(0xffffffffu, r0, 1));
        r0 = fmaxf(r0, __shfl_xor_sync(0xffffffffu, r0, 2));
        r1 = fmaxf(r1, __shfl_xor_sync(0xffffffffu, r1, 1));
        r1 = fmaxf(r1, __shfl_xor_sync(0xffffffffu, r1, 2));

        float mn0 = fmaxf(m0, r0), mn1 = fmaxf(m1, r1);
        float sc0 = ex2(m0 - mn0), sc1 = ex2(m1 - mn1);
        m0 = mn0; m1 = mn1;

        float ls0 = 0.f, ls1 = 0.f;
#pragma unroll
        for (int g = 0; g < 8; g++) {
            c[g][0] = ex2(c[g][0] - m0);
            c[g][1] = ex2(c[g][1] - m0);
            c[g][2] = ex2(c[g][2] - m1);
            c[g][3] = ex2(c[g][3] - m1);
            ls0 += c[g][0] + c[g][1];
            ls1 += c[g][2] + c[g][3];
            o[g][0] *= sc0; o[g][1] *= sc0;
            o[g][2] *= sc1; o[g][3] *= sc1;
        }
        l0 = l0 * sc0 + ls0;
        l1 = l1 * sc1 + ls1;

        // ---- P -> bf16 hi/lo A-frags ----
        uint32_t ph[4][4], pl[4][4];
#pragma unroll
        for (int kk = 0; kk < 4; kk++) {
            pack_hilo(c[2*kk][0],   c[2*kk][1],   ph[kk][0], pl[kk][0]);
            pack_hilo(c[2*kk][2],   c[2*kk][3],   ph[kk][1], pl[kk][1]);
            pack_hilo(c[2*kk+1][0], c[2*kk+1][1], ph[kk][2], pl[kk][2]);
            pack_hilo(c[2*kk+1][2], c[2*kk+1][3], ph[kk][3], pl[kk][3]);
        }

        // ---- O += P @ V^T : o[g] covers dims 8g..8g+7 (3 split terms) ----
#pragma unroll
        for (int g = 0; g < 8; g++) {
            uint32_t base = vb[cur] + g * 8 * VSTRIDE;
#pragma unroll
            for (int kk = 0; kk < 4; kk++) {
                uint32_t v[4];                 // vh0,vh1 | vl0,vl1
                ldm_x4(v, base + kk * 32);
                mma16816(o[g], ph[kk], v[0], v[1]);
                mma16816(o[g], pl[kk], v[0], v[1]);
                mma16816(o[g], ph[kk], v[2], v[3]);
            }
        }
        __syncthreads();   // stage `cur` free before it is refilled next iter
    }

    // ---- epilogue ----
    l0 += __shfl_xor_sync(0xffffffffu, l0, 1);
    l0 += __shfl_xor_sync(0xffffffffu, l0, 2);
    l1 += __shfl_xor_sync(0xffffffffu, l1, 1);
    l1 += __shfl_xor_sync(0xffffffffu, l1, 2);
    const float inv0 = 1.0f / (l0 * 64.0f);   // 64 = sqrt(4096)
    const float inv1 = 1.0f / (l1 * 64.0f);

    const int r0row = q0 + wid * 16 + (lane >> 2);
    const int r1row = r0row + 8;
    const int dcol  = 2 * (lane & 3);
#pragma unroll
    for (int g = 0; g < 8; g++) {
        int d = 8 * g + dcol;
        *reinterpret_cast<float2*>(&g_O[h][r0row][d]) = make_float2(o[g][0]*inv0, o[g][1]*inv0);
        *reinterpret_cast<float2*>(&g_O[h][r1row][d]) = make_float2(o[g][2]*inv1, o[g][3]*inv1);
    }
}

// ---------------------------------------------------------------------------
// Kernel 3: output projection. grid (NN/64, 2), 64 threads.
// ---------------------------------------------------------------------------
__global__ __launch_bounds__(64)
void out_kernel(const float* __restrict__ W_ao, const float* __restrict__ W_vo,
                float* __restrict__ out)
{
    const int n = blockIdx.x * 64 + threadIdx.x;
    const int z = blockIdx.y;

    if (z == 0) {
        __shared__ float s_ao[H * ADIM * CHAN];
        for (int t = threadIdx.x; t < H * ADIM * CHAN; t += 64) s_ao[t] = W_ao[t];
        __syncthreads();
        float acc[ADIM];
#pragma unroll
        for (int j = 0; j < ADIM; j++) acc[j] = 0.f;
        for (int h = 0; h < H; h++) {
            const float* O = &g_O[h][n][0];
            const float* w = s_ao + h * ADIM * CHAN;
#pragma unroll
            for (int i = 0; i < CHAN; i++) {
                float oi = O[i];
#pragma unroll
                for (int j = 0; j < ADIM; j++) acc[j] += w[j * CHAN + i] * oi;
            }
        }
#pragma unroll
        for (int j = 0; j < ADIM / 4; j++)
            reinterpret_cast<float4*>(out + n * ADIM)[j] =
                make_float4(acc[4*j], acc[4*j+1], acc[4*j+2], acc[4*j+3]);
    } else {
        __shared__ float s_vo[H * VDIM * CHAN];
        for (int t = threadIdx.x; t < H * VDIM * CHAN; t += 64) s_vo[t] = W_vo[t];
        __syncthreads();
        float acc[VDIM * 3];
#pragma unroll
        for (int j = 0; j < VDIM * 3; j++) acc[j] = 0.f;
        for (int h = 0; h < H; h++) {
            const float* O = &g_O[h][n][0];
            const float* w = s_vo + h * VDIM * CHAN;
#pragma unroll
            for (int c = 0; c < CHAN; c++) {
                float o0 = O[16 + 3*c], o1 = O[17 + 3*c], o2 = O[18 + 3*c];
#pragma unroll
                for (int j = 0; j < VDIM; j++) {
                    float ww = w[j * CHAN + c];
                    acc[j*3]   += ww * o0;
                    acc[j*3+1] += ww * o1;
                    acc[j*3+2] += ww * o2;
                }
            }
        }
        float* vo = out + NN * ADIM + n * VDIM * 3;
#pragma unroll
        for (int j = 0; j < VDIM * 3; j++) vo[j] = acc[j];
    }
}

// ---------------------------------------------------------------------------
extern "C" void kernel_launch(void* const* d_in, const int* in_sizes, int n_in,
                              void* d_out, int out_size)
{
    const float* ax    = (const float*)d_in[0];
    const float* vx    = (const float*)d_in[1];
    const float* pos_k = (const float*)d_in[2];
    const float* pos_q = (const float*)d_in[3];
    const float* W_aq  = (const float*)d_in[4];
    const float* W_vq  = (const float*)d_in[5];
    const float* W_ak  = (const float*)d_in[6];
    const float* W_vk  = (const float*)d_in[7];
    const float* W_av  = (const float*)d_in[8];
    const float* W_vv  = (const float*)d_in[9];
    const float* W_ao  = (const float*)d_in[10];
    const float* W_vo  = (const float*)d_in[11];
    float* out = (float*)d_out;

    cudaFuncSetAttribute(attn_kernel, cudaFuncAttributeMaxDynamicSharedMemorySize,
                         SMEM_BYTES);

    proj_kernel<<<dim3(NN / 64, H, 3), 64>>>(ax, vx, pos_q, pos_k,
                                             W_aq, W_vq, W_ak, W_vk, W_av, W_vv);
    vtrans_kernel<<<dim3(NN / 64, H), 256>>>();
    attn_kernel<<<dim3(NN / QT, H), 128, SMEM_BYTES>>>();
    out_kernel<<<dim3(NN / 64, 2), 64>>>(W_ao, W_vo, out);
}

// round 6
// speedup vs baseline: 4.0628x; 1.0916x over previous
#include <cuda_runtime.h>
#include <cuda_bf16.h>
#include <cstdint>
#include <math.h>

#define H    4
#define NN   4096
#define CHAN 16
#define ADIM 64
#define VDIM 16
#define D    64
#define EXT  80          // 64 feature dims + 5 bias dims + zero pad (5 ksteps of 16)
#define QT   64          // query rows per CTA (16 per warp)
#define KT   64          // key tile
#define NT   (NN / KT)   // 64 key tiles

#define LOG2E 1.4426950408889634f

// ---------------- device global scratch (no runtime alloc allowed) ----------
__device__ __align__(16) __nv_bfloat16 g_Qe[2][H][NN][EXT];   // hi/lo split (Q pre-scaled by log2e)
__device__ __align__(16) __nv_bfloat16 g_Ke[2][H][NN][EXT];
__device__ __align__(16) __nv_bfloat16 g_Vt[2][H][D][NN];     // transposed, hi/lo
__device__ __align__(16) float         g_O [H][NN][D];

// ---------------- helpers ---------------------------------------------------
__device__ __forceinline__ uint32_t smem_u32(const void* p) {
    uint32_t a;
    asm("{ .reg .u64 t; cvta.to.shared.u64 t, %1; cvt.u32.u64 %0, t; }" : "=r"(a) : "l"(p));
    return a;
}
__device__ __forceinline__ void ldm_x4(uint32_t* r, uint32_t addr) {
    asm volatile("ldmatrix.sync.aligned.m8n8.x4.shared.b16 {%0,%1,%2,%3}, [%4];"
                 : "=r"(r[0]), "=r"(r[1]), "=r"(r[2]), "=r"(r[3]) : "r"(addr));
}
__device__ __forceinline__ void mma16816(float* c, const uint32_t* a,
                                         uint32_t b0, uint32_t b1) {
    asm volatile("mma.sync.aligned.m16n8k16.row.col.f32.bf16.bf16.f32 "
                 "{%0,%1,%2,%3}, {%4,%5,%6,%7}, {%8,%9}, {%0,%1,%2,%3};"
                 : "+f"(c[0]), "+f"(c[1]), "+f"(c[2]), "+f"(c[3])
                 : "r"(a[0]), "r"(a[1]), "r"(a[2]), "r"(a[3]), "r"(b0), "r"(b1));
}
__device__ __forceinline__ uint32_t pack_bf16x2(float x0, float x1) {
    uint32_t r;
    asm("cvt.rn.bf16x2.f32 %0, %1, %2;" : "=r"(r) : "f"(x1), "f"(x0));
    return r;
}
__device__ __forceinline__ void pack_hilo(float x0, float x1, uint32_t& hi, uint32_t& lo) {
    asm("cvt.rn.bf16x2.f32 %0, %1, %2;" : "=r"(hi) : "f"(x1), "f"(x0));
    float f0 = __uint_as_float(hi << 16);
    float f1 = __uint_as_float(hi & 0xffff0000u);
    asm("cvt.rn.bf16x2.f32 %0, %1, %2;" : "=r"(lo) : "f"(x1 - f1), "f"(x0 - f0));
}
__device__ __forceinline__ float ex2(float x) {
    float y;
    asm("ex2.approx.f32 %0, %1;" : "=f"(y) : "f"(x));
    return y;
}
__device__ __forceinline__ void cp16(uint32_t saddr, const void* gaddr) {
    asm volatile("cp.async.ca.shared.global [%0], [%1], 16;" :: "r"(saddr), "l"(gaddr) : "memory");
}
#define CP_COMMIT() asm volatile("cp.async.commit_group;" ::: "memory")
#define CP_WAIT1()  asm volatile("cp.async.wait_group 1;"  ::: "memory")
#define CP_WAIT0()  asm volatile("cp.async.wait_group 0;"  ::: "memory")

// padded smem row strides (conflict-free ldmatrix)
#define KSTRIDE 176      // 160B data + 16B pad
#define VSTRIDE 144      // 128B data + 16B pad
#define KB_HL   (64 * KSTRIDE)                 // 11264 per hi/lo plane
#define VB_HL   (64 * VSTRIDE)                 // 9216
#define STAGE_BYTES (2 * KB_HL + 2 * VB_HL)    // 40960
#define SMEM_BYTES  (2 * STAGE_BYTES)          // 81920

// ---------------------------------------------------------------------------
// Kernel 1: projection -> Qext/Kext (bf16 hi/lo); V computed AND transposed
// in-block to g_Vt (hi/lo).  grid (NN/64, H, 3), 64 threads.
// ---------------------------------------------------------------------------
__global__ __launch_bounds__(64)
void proj_kernel(const float* __restrict__ ax, const float* __restrict__ vx,
                 const float* __restrict__ pos_q, const float* __restrict__ pos_k,
                 const float* __restrict__ W_aq, const float* __restrict__ W_vq,
                 const float* __restrict__ W_ak, const float* __restrict__ W_vk,
                 const float* __restrict__ W_av, const float* __restrict__ W_vv)
{
    const int h  = blockIdx.y;
    const int z  = blockIdx.z;          // 0=Q 1=K 2=V
    const int n0 = blockIdx.x * 64;
    const int n  = n0 + threadIdx.x;

    const float* Wa = (z == 0) ? W_aq : (z == 1) ? W_ak : W_av;
    const float* Wv = (z == 0) ? W_vq : (z == 1) ? W_vk : W_vv;

    __shared__ float s_a[CHAN * ADIM];
    __shared__ float s_v[CHAN * VDIM];
    __shared__ float ts[64][65];        // V transpose tile (z==2 only)

    for (int t = threadIdx.x; t < CHAN * ADIM; t += 64) s_a[t] = Wa[h * CHAN * ADIM + t];
    for (int t = threadIdx.x; t < CHAN * VDIM; t += 64) s_v[t] = Wv[h * CHAN * VDIM + t];
    __syncthreads();

    float a[ADIM];
#pragma unroll
    for (int j = 0; j < ADIM / 4; j++) {
        float4 t = reinterpret_cast<const float4*>(ax + n * ADIM)[j];
        a[4*j] = t.x; a[4*j+1] = t.y; a[4*j+2] = t.z; a[4*j+3] = t.w;
    }
    float v[VDIM][3];
#pragma unroll
    for (int j = 0; j < VDIM; j++) {
        v[j][0] = vx[(n * VDIM + j) * 3 + 0];
        v[j][1] = vx[(n * VDIM + j) * 3 + 1];
        v[j][2] = vx[(n * VDIM + j) * 3 + 2];
    }

    float e[EXT];
#pragma unroll
    for (int c = 0; c < CHAN; c++) {
        float s0 = 0.f;
#pragma unroll
        for (int j = 0; j < ADIM; j++) s0 += s_a[c * ADIM + j] * a[j];
        float s1 = 0.f, s2 = 0.f, s3 = 0.f;
#pragma unroll
        for (int j = 0; j < VDIM; j++) {
            float w = s_v[c * VDIM + j];
            s1 += w * v[j][0]; s2 += w * v[j][1]; s3 += w * v[j][2];
        }
        if (z < 2) {
            float nsq = s0*s0 + s1*s1 + s2*s2 + s3*s3;
            float sc  = rsqrtf(sqrtf(1.0f + nsq));
            s0 *= sc; s1 *= sc; s2 *= sc; s3 *= sc;
        }
        e[4*c] = s0; e[4*c+1] = s1; e[4*c+2] = s2; e[4*c+3] = s3;
    }

    if (z == 2) {   // V: transpose through smem, write g_Vt hi/lo directly
#pragma unroll
        for (int j = 0; j < D; j++) ts[threadIdx.x][j] = e[j];
        __syncthreads();
        const int d = threadIdx.x;
        uint32_t hw[32], lw[32];
#pragma unroll
        for (int p = 0; p < 32; p++)
            pack_hilo(ts[2*p][d], ts[2*p+1][d], hw[p], lw[p]);
#pragma unroll
        for (int w = 0; w < 8; w++) {
            ((uint4*)&g_Vt[0][h][d][n0])[w] = ((const uint4*)hw)[w];
            ((uint4*)&g_Vt[1][h][d][n0])[w] = ((const uint4*)lw)[w];
        }
        return;
    }

    // bias extension dims
    const float invr = 1.0f / (float)(1 << (2 * h));
#pragma unroll
    for (int j = D; j < EXT; j++) e[j] = 0.f;
    if (z == 0) {   // Q side: [2*invr*pq, -invr, -invr], scaled by log2e
        const float* pq = pos_q + (h * NN + n) * 3;
        e[64] = 2.f * invr * pq[0];
        e[65] = 2.f * invr * pq[1];
        e[66] = 2.f * invr * pq[2];
        e[67] = -invr;
        e[68] = -invr;
#pragma unroll
        for (int j = 0; j < EXT; j++) e[j] *= LOG2E;
    } else {        // K side: [pk, split(|pk|^2)]
        const float* pk = pos_k + (h * NN + n) * 3;
        e[64] = pk[0]; e[65] = pk[1]; e[66] = pk[2];
        float w = pk[0]*pk[0] + pk[1]*pk[1] + pk[2]*pk[2];
        float whi = __bfloat162float(__float2bfloat16(w));
        e[67] = whi;
        e[68] = w - whi;
    }

    __nv_bfloat16* dhi = (z == 0) ? &g_Qe[0][h][n][0] : &g_Ke[0][h][n][0];
    __nv_bfloat16* dlo = (z == 0) ? &g_Qe[1][h][n][0] : &g_Ke[1][h][n][0];
#pragma unroll
    for (int j = 0; j < EXT; j++) {
        __nv_bfloat16 hi = __float2bfloat16(e[j]);
        dhi[j] = hi;
        dlo[j] = __float2bfloat16(e[j] - __bfloat162float(hi));
    }
}

// ---------------------------------------------------------------------------
// Kernel 2: HMMA flash attention, cp.async double-buffered.
// grid (NN/QT, H), 128 threads (4 warps), warp w owns rows q0+16w..16w+15.
// ---------------------------------------------------------------------------
__global__ __launch_bounds__(128)
void attn_kernel()
{
    extern __shared__ __align__(16) uint8_t smem[];

    const int tid  = threadIdx.x;
    const int wid  = tid >> 5;
    const int lane = tid & 31;
    const int h    = blockIdx.y;
    const int q0   = blockIdx.x * QT;

    const uint32_t sbase = smem_u32(smem);

    // ---- stage Q tile into stage-0 K buffers, pull A-frags ----
    for (int u = tid; u < 64 * 10; u += 128) {
        int row = u / 10, w = u - row * 10;
        uint32_t off = row * KSTRIDE + w * 16;
        *(uint4*)(smem + off)         = ((const uint4*)&g_Qe[0][h][q0 + row][0])[w];
        *(uint4*)(smem + KB_HL + off) = ((const uint4*)&g_Qe[1][h][q0 + row][0])[w];
    }
    __syncthreads();

    uint32_t qh[5][4], ql[5][4];
    {
        uint32_t qoff = (wid * 16 + (lane & 15)) * KSTRIDE + (lane >> 4) * 16;
#pragma unroll
        for (int ks = 0; ks < 5; ks++) {
            ldm_x4(qh[ks], sbase + qoff + ks * 32);
            ldm_x4(ql[ks], sbase + KB_HL + qoff + ks * 32);
        }
    }
    __syncthreads();   // Q reads done before prefetch overwrites stage 0

    // per-lane ldmatrix bases (B-frags, hi/lo planes fused into one x4)
    const int hl = (lane >> 4) & 1;
    uint32_t kb[2], vb[2];
#pragma unroll
    for (int s = 0; s < 2; s++) {
        kb[s] = sbase + s * STAGE_BYTES + (hl ? KB_HL : 0)
              + (lane & 7) * KSTRIDE + ((lane >> 3) & 1) * 16;
        vb[s] = sbase + s * STAGE_BYTES + 2 * KB_HL + (hl ? VB_HL : 0)
              + (lane & 7) * VSTRIDE + ((lane >> 3) & 1) * 16;
    }

    auto prefetch = [&](int t, int s) {
        const int j0 = t * KT;
        const uint32_t kB = sbase + s * STAGE_BYTES;
        for (int u = tid; u < 64 * 10; u += 128) {
            int row = u / 10, w = u - row * 10;
            uint32_t off = kB + row * KSTRIDE + w * 16;
            cp16(off,          &g_Ke[0][h][j0 + row][w * 8]);
            cp16(off + KB_HL,  &g_Ke[1][h][j0 + row][w * 8]);
        }
        const uint32_t vB = kB + 2 * KB_HL;
        for (int u = tid; u < 64 * 8; u += 128) {
            int row = u >> 3, w = u & 7;
            uint32_t off = vB + row * VSTRIDE + w * 16;
            cp16(off,          &g_Vt[0][h][row][j0 + w * 8]);
            cp16(off + VB_HL,  &g_Vt[1][h][row][j0 + w * 8]);
        }
    };

    float m0 = -INFINITY, m1 = -INFINITY, l0 = 0.f, l1 = 0.f;
    float o[8][4];
#pragma unroll
    for (int g = 0; g < 8; g++) { o[g][0]=0.f; o[g][1]=0.f; o[g][2]=0.f; o[g][3]=0.f; }

    prefetch(0, 0);
    CP_COMMIT();

    for (int t = 0; t < NT; t++) {
        const int cur = t & 1;
        if (t + 1 < NT) {
            prefetch(t + 1, cur ^ 1);
            CP_COMMIT();
            CP_WAIT1();
        } else {
            CP_WAIT0();
        }
        __syncthreads();

        // ---- S = Qext @ Kext^T (3 split terms, 5 ksteps, 8 col groups) ----
        float c[8][4];
#pragma unroll
        for (int g = 0; g < 8; g++) { c[g][0]=0.f; c[g][1]=0.f; c[g][2]=0.f; c[g][3]=0.f; }
#pragma unroll
        for (int g = 0; g < 8; g++) {
            uint32_t base = kb[cur] + g * 8 * KSTRIDE;
#pragma unroll
            for (int ks = 0; ks < 5; ks++) {
                uint32_t b[4];                 // bh0,bh1 | bl0,bl1
                ldm_x4(b, base + ks * 32);
                mma16816(c[g], qh[ks], b[0], b[1]);
                mma16816(c[g], ql[ks], b[0], b[1]);
                mma16816(c[g], qh[ks], b[2], b[3]);
            }
        }

        // ---- online softmax (log2 domain) ----
        float r0 = -INFINITY, r1 = -INFINITY;
#pragma unroll
        for (int g = 0; g < 8; g++) {
            r0 = fmaxf(r0, fmaxf(c[g][0], c[g][1]));
            r1 = fmaxf(r1, fmaxf(c[g][2], c[g][3]));
        }
        r0 = fmaxf(r0, __shfl_xor_sync(0xffffffffu, r0, 1));
        r0 = fmaxf(r0, __shfl_xor_sync(0xffffffffu, r0, 2));
        r1 = fmaxf(r1, __shfl_xor_sync(0xffffffffu, r1, 1));
        r1 = fmaxf(r1, __shfl_xor_sync(0xffffffffu, r1, 2));

        float mn0 = fmaxf(m0, r0), mn1 = fmaxf(m1, r1);
        if (__any_sync(0xffffffffu, (mn0 > m0) | (mn1 > m1))) {
            float sc0 = ex2(m0 - mn0), sc1 = ex2(m1 - mn1);
            l0 *= sc0; l1 *= sc1;
#pragma unroll
            for (int g = 0; g < 8; g++) {
                o[g][0] *= sc0; o[g][1] *= sc0;
                o[g][2] *= sc1; o[g][3] *= sc1;
            }
        }
        m0 = mn0; m1 = mn1;

        float ls0 = 0.f, ls1 = 0.f;
#pragma unroll
        for (int g = 0; g < 8; g++) {
            c[g][0] = ex2(c[g][0] - m0);
            c[g][1] = ex2(c[g][1] - m0);
            c[g][2] = ex2(c[g][2] - m1);
            c[g][3] = ex2(c[g][3] - m1);
            ls0 += c[g][0] + c[g][1];
            ls1 += c[g][2] + c[g][3];
        }
        l0 += ls0;
        l1 += ls1;

        // ---- P -> single bf16 A-frags (dominant key is exact: p = 2^0) ----
        uint32_t ph[4][4];
#pragma unroll
        for (int kk = 0; kk < 4; kk++) {
            ph[kk][0] = pack_bf16x2(c[2*kk][0],   c[2*kk][1]);
            ph[kk][1] = pack_bf16x2(c[2*kk][2],   c[2*kk][3]);
            ph[kk][2] = pack_bf16x2(c[2*kk+1][0], c[2*kk+1][1]);
            ph[kk][3] = pack_bf16x2(c[2*kk+1][2], c[2*kk+1][3]);
        }

        // ---- O += P @ V^T (V hi + V lo terms) ----
#pragma unroll
        for (int g = 0; g < 8; g++) {
            uint32_t base = vb[cur] + g * 8 * VSTRIDE;
#pragma unroll
            for (int kk = 0; kk < 4; kk++) {
                uint32_t v[4];                 // vh0,vh1 | vl0,vl1
                ldm_x4(v, base + kk * 32);
                mma16816(o[g], ph[kk], v[0], v[1]);
                mma16816(o[g], ph[kk], v[2], v[3]);
            }
        }
        __syncthreads();
    }

    // ---- epilogue ----
    l0 += __shfl_xor_sync(0xffffffffu, l0, 1);
    l0 += __shfl_xor_sync(0xffffffffu, l0, 2);
    l1 += __shfl_xor_sync(0xffffffffu, l1, 1);
    l1 += __shfl_xor_sync(0xffffffffu, l1, 2);
    const float inv0 = 1.0f / (l0 * 64.0f);   // 64 = sqrt(4096)
    const float inv1 = 1.0f / (l1 * 64.0f);

    const int r0row = q0 + wid * 16 + (lane >> 2);
    const int r1row = r0row + 8;
    const int dcol  = 2 * (lane & 3);
#pragma unroll
    for (int g = 0; g < 8; g++) {
        int d = 8 * g + dcol;
        *reinterpret_cast<float2*>(&g_O[h][r0row][d]) = make_float2(o[g][0]*inv0, o[g][1]*inv0);
        *reinterpret_cast<float2*>(&g_O[h][r1row][d]) = make_float2(o[g][2]*inv1, o[g][3]*inv1);
    }
}

// ---------------------------------------------------------------------------
// Kernel 3: output projection, thread per output element.
// a_out: 4096*64 elems, v_out: 4096*48 elems -> 458752 threads.
// ---------------------------------------------------------------------------
#define A_ELEMS (NN * ADIM)         // 262144
#define O_ELEMS (A_ELEMS + NN * VDIM * 3)

__global__ __launch_bounds__(256)
void out_kernel(const float* __restrict__ W_ao, const float* __restrict__ W_vo,
                float* __restrict__ out)
{
    __shared__ float s_ao[H * ADIM * CHAN];   // 4096
    __shared__ float s_vo[H * VDIM * CHAN];   // 1024
    for (int t = threadIdx.x; t < H * ADIM * CHAN; t += 256) s_ao[t] = W_ao[t];
    for (int t = threadIdx.x; t < H * VDIM * CHAN; t += 256) s_vo[t] = W_vo[t];
    __syncthreads();

    const int gid = blockIdx.x * 256 + threadIdx.x;
    if (gid < A_ELEMS) {
        const int n = gid >> 6, j = gid & 63;
        float acc = 0.f;
#pragma unroll
        for (int h = 0; h < H; h++) {
            const float* O = &g_O[h][n][0];
            const float* w = s_ao + h * ADIM * CHAN + j * CHAN;
#pragma unroll
            for (int i = 0; i < CHAN; i++) acc += w[i] * O[i];
        }
        out[gid] = acc;
    } else {
        const int idx = gid - A_ELEMS;
        const int n = idx / 48, jv = idx - n * 48;
        const int j = jv / 3, vv = jv - j * 3;
        float acc = 0.f;
#pragma unroll
        for (int h = 0; h < H; h++) {
            const float* O = &g_O[h][n][CHAN + vv];
            const float* w = s_vo + h * VDIM * CHAN + j * CHAN;
#pragma unroll
            for (int c = 0; c < CHAN; c++) acc += w[c] * O[3 * c];
        }
        out[gid] = acc;
    }
}

// ---------------------------------------------------------------------------
extern "C" void kernel_launch(void* const* d_in, const int* in_sizes, int n_in,
                              void* d_out, int out_size)
{
    const float* ax    = (const float*)d_in[0];
    const float* vx    = (const float*)d_in[1];
    const float* pos_k = (const float*)d_in[2];
    const float* pos_q = (const float*)d_in[3];
    const float* W_aq  = (const float*)d_in[4];
    const float* W_vq  = (const float*)d_in[5];
    const float* W_ak  = (const float*)d_in[6];
    const float* W_vk  = (const float*)d_in[7];
    const float* W_av  = (const float*)d_in[8];
    const float* W_vv  = (const float*)d_in[9];
    const float* W_ao  = (const float*)d_in[10];
    const float* W_vo  = (const float*)d_in[11];
    float* out = (float*)d_out;

    cudaFuncSetAttribute(attn_kernel, cudaFuncAttributeMaxDynamicSharedMemorySize,
                         SMEM_BYTES);

    proj_kernel<<<dim3(NN / 64, H, 3), 64>>>(ax, vx, pos_q, pos_k,
                                             W_aq, W_vq, W_ak, W_vk, W_av, W_vv);
    attn_kernel<<<dim3(NN / QT, H), 128, SMEM_BYTES>>>();
    out_kernel<<<(O_ELEMS + 255) / 256, 256>>>(W_ao, W_vo, out);
}

// round 7
// speedup vs baseline: 4.6852x; 1.1532x over previous
#include <cuda_runtime.h>
#include <cuda_bf16.h>
#include <cstdint>
#include <math.h>

#define H    4
#define NN   4096
#define CHAN 16
#define ADIM 64
#define VDIM 16
#define D    64
#define EXT  80          // 64 feature dims + 5 bias dims + zero pad (5 ksteps of 16)
#define QT   128         // query rows per CTA (32 per warp, 2 rowsets of 16)
#define KT   64          // key tile
#define NSPLIT 2
#define NT2  (NN / KT / NSPLIT)   // 32 tiles per split

#define LOG2E 1.4426950408889634f

// ---------------- device global scratch (no runtime alloc allowed) ----------
__device__ __align__(16) __nv_bfloat16 g_Qe[2][H][NN][EXT];
__device__ __align__(16) __nv_bfloat16 g_Ke[2][H][NN][EXT];
__device__ __align__(16) __nv_bfloat16 g_Vt[2][H][D][NN];
__device__ __align__(16) float         g_O [H][NN][D];
__device__ float g_pm[NSPLIT * H * NN];
__device__ float g_pl[NSPLIT * H * NN];
__device__ __align__(16) float g_pO[NSPLIT][H][NN][D];

// ---------------- helpers ---------------------------------------------------
__device__ __forceinline__ uint32_t smem_u32(const void* p) {
    uint32_t a;
    asm("{ .reg .u64 t; cvta.to.shared.u64 t, %1; cvt.u32.u64 %0, t; }" : "=r"(a) : "l"(p));
    return a;
}
__device__ __forceinline__ void ldm_x4(uint32_t* r, uint32_t addr) {
    asm volatile("ldmatrix.sync.aligned.m8n8.x4.shared.b16 {%0,%1,%2,%3}, [%4];"
                 : "=r"(r[0]), "=r"(r[1]), "=r"(r[2]), "=r"(r[3]) : "r"(addr));
}
__device__ __forceinline__ void mma16816(float* c, const uint32_t* a,
                                         uint32_t b0, uint32_t b1) {
    asm volatile("mma.sync.aligned.m16n8k16.row.col.f32.bf16.bf16.f32 "
                 "{%0,%1,%2,%3}, {%4,%5,%6,%7}, {%8,%9}, {%0,%1,%2,%3};"
                 : "+f"(c[0]), "+f"(c[1]), "+f"(c[2]), "+f"(c[3])
                 : "r"(a[0]), "r"(a[1]), "r"(a[2]), "r"(a[3]), "r"(b0), "r"(b1));
}
__device__ __forceinline__ void pack_hilo(float x0, float x1, uint32_t& hi, uint32_t& lo) {
    asm("cvt.rn.bf16x2.f32 %0, %1, %2;" : "=r"(hi) : "f"(x1), "f"(x0));
    float f0 = __uint_as_float(hi << 16);
    float f1 = __uint_as_float(hi & 0xffff0000u);
    asm("cvt.rn.bf16x2.f32 %0, %1, %2;" : "=r"(lo) : "f"(x1 - f1), "f"(x0 - f0));
}
__device__ __forceinline__ float ex2(float x) {
    float y;
    asm("ex2.approx.f32 %0, %1;" : "=f"(y) : "f"(x));
    return y;
}
__device__ __forceinline__ void cp16(uint32_t saddr, const void* gaddr) {
    asm volatile("cp.async.ca.shared.global [%0], [%1], 16;" :: "r"(saddr), "l"(gaddr) : "memory");
}
#define CP_COMMIT() asm volatile("cp.async.commit_group;" ::: "memory")
#define CP_WAIT1()  asm volatile("cp.async.wait_group 1;"  ::: "memory")
#define CP_WAIT0()  asm volatile("cp.async.wait_group 0;"  ::: "memory")

#define KSTRIDE 176
#define VSTRIDE 144
#define KB_HL   (64 * KSTRIDE)
#define VB_HL   (64 * VSTRIDE)
#define STAGE_BYTES (2 * KB_HL + 2 * VB_HL)    // 40960
#define SMEM_BYTES  (2 * STAGE_BYTES)          // 81920

// ---------------------------------------------------------------------------
// Kernel 1: projection. grid (NN/64, H, 3), 256 threads.
// thread = (token nl = tid>>2, channel quad cq = tid&3).
// ---------------------------------------------------------------------------
__global__ __launch_bounds__(256)
void proj_kernel(const float* __restrict__ ax, const float* __restrict__ vx,
                 const float* __restrict__ pos_q, const float* __restrict__ pos_k,
                 const float* __restrict__ W_aq, const float* __restrict__ W_vq,
                 const float* __restrict__ W_ak, const float* __restrict__ W_vk,
                 const float* __restrict__ W_av, const float* __restrict__ W_vv)
{
    const int h  = blockIdx.y;
    const int z  = blockIdx.z;          // 0=Q 1=K 2=V
    const int n0 = blockIdx.x * 64;
    const int tid = threadIdx.x;

    const float* Wa = (z == 0) ? W_aq : (z == 1) ? W_ak : W_av;
    const float* Wv = (z == 0) ? W_vq : (z == 1) ? W_vk : W_vv;

    __shared__ float s_wa[CHAN * 65];
    __shared__ float s_wv[CHAN * 17];
    __shared__ float s_ax[64 * 65];
    __shared__ float s_vx[64 * 49];
    __shared__ float ts[64][68];        // z==2 transpose staging

    for (int t = tid; t < CHAN * ADIM; t += 256)
        s_wa[(t >> 6) * 65 + (t & 63)] = Wa[h * CHAN * ADIM + t];
    for (int t = tid; t < CHAN * VDIM; t += 256)
        s_wv[(t >> 4) * 17 + (t & 15)] = Wv[h * CHAN * VDIM + t];
    for (int t = tid; t < 64 * ADIM; t += 256)
        s_ax[(t >> 6) * 65 + (t & 63)] = ax[(size_t)n0 * ADIM + t];
    for (int t = tid; t < 64 * VDIM * 3; t += 256)
        s_vx[(t / 48) * 49 + (t % 48)] = vx[(size_t)n0 * VDIM * 3 + t];
    __syncthreads();

    const int nl = tid >> 2;
    const int cq = tid & 3;
    const int n  = n0 + nl;
    const float fz = (z == 0) ? LOG2E : 1.0f;

    uint32_t hw[8], lw[8];
    float vout[16];
#pragma unroll
    for (int cc = 0; cc < 4; cc++) {
        const int c = cq * 4 + cc;
        const float* wa = s_wa + c * 65;
        const float* wv = s_wv + c * 17;
        const float* arow = s_ax + nl * 65;
        const float* vrow = s_vx + nl * 49;
        float s0 = 0.f;
#pragma unroll
        for (int j = 0; j < ADIM; j++) s0 += wa[j] * arow[j];
        float s1 = 0.f, s2 = 0.f, s3 = 0.f;
#pragma unroll
        for (int j = 0; j < VDIM; j++) {
            float w = wv[j];
            s1 += w * vrow[3*j+0]; s2 += w * vrow[3*j+1]; s3 += w * vrow[3*j+2];
        }
        if (z < 2) {
            float nsq = s0*s0 + s1*s1 + s2*s2 + s3*s3;
            float sc  = rsqrtf(sqrtf(1.0f + nsq)) * fz;
            s0 *= sc; s1 *= sc; s2 *= sc; s3 *= sc;
        }
        if (z == 2) {
            vout[4*cc] = s0; vout[4*cc+1] = s1; vout[4*cc+2] = s2; vout[4*cc+3] = s3;
        } else {
            pack_hilo(s0, s1, hw[2*cc],   lw[2*cc]);
            pack_hilo(s2, s3, hw[2*cc+1], lw[2*cc+1]);
        }
    }

    if (z == 2) {
#pragma unroll
        for (int i = 0; i < 16; i++) ts[nl][cq * 16 + i] = vout[i];
        __syncthreads();
        const int d = tid & 63, q = tid >> 6;   // dim, token quarter
        uint32_t th[8], tl[8];
#pragma unroll
        for (int p = 0; p < 8; p++)
            pack_hilo(ts[16*q + 2*p][d], ts[16*q + 2*p + 1][d], th[p], tl[p]);
        uint4* dh = (uint4*)&g_Vt[0][h][d][n0 + 16*q];
        uint4* dl = (uint4*)&g_Vt[1][h][d][n0 + 16*q];
        dh[0] = ((const uint4*)th)[0]; dh[1] = ((const uint4*)th)[1];
        dl[0] = ((const uint4*)tl)[0]; dl[1] = ((const uint4*)tl)[1];
        return;
    }

    // main channel write: dims 16cq..16cq+15
    __nv_bfloat16* bh = (z == 0) ? &g_Qe[0][h][n][16*cq] : &g_Ke[0][h][n][16*cq];
    __nv_bfloat16* bl = (z == 0) ? &g_Qe[1][h][n][16*cq] : &g_Ke[1][h][n][16*cq];
    ((uint4*)bh)[0] = ((const uint4*)hw)[0]; ((uint4*)bh)[1] = ((const uint4*)hw)[1];
    ((uint4*)bl)[0] = ((const uint4*)lw)[0]; ((uint4*)bl)[1] = ((const uint4*)lw)[1];

    // bias extension dims 64..79 (thread per token)
    if (tid < 64) {
        const int nb = n0 + tid;
        float e[16];
#pragma unroll
        for (int j = 0; j < 16; j++) e[j] = 0.f;
        const float invr = 1.0f / (float)(1 << (2 * h));
        if (z == 0) {
            const float* pq = pos_q + (h * NN + nb) * 3;
            e[0] = 2.f * invr * pq[0] * LOG2E;
            e[1] = 2.f * invr * pq[1] * LOG2E;
            e[2] = 2.f * invr * pq[2] * LOG2E;
            e[3] = -invr * LOG2E;
            e[4] = -invr * LOG2E;
        } else {
            const float* pk = pos_k + (h * NN + nb) * 3;
            e[0] = pk[0]; e[1] = pk[1]; e[2] = pk[2];
            float w = pk[0]*pk[0] + pk[1]*pk[1] + pk[2]*pk[2];
            float whi = __bfloat162float(__float2bfloat16(w));
            e[3] = whi;
            e[4] = w - whi;
        }
        uint32_t ehw[8], elw[8];
#pragma unroll
        for (int p = 0; p < 8; p++) pack_hilo(e[2*p], e[2*p+1], ehw[p], elw[p]);
        __nv_bfloat16* xh = (z == 0) ? &g_Qe[0][h][nb][64] : &g_Ke[0][h][nb][64];
        __nv_bfloat16* xl = (z == 0) ? &g_Qe[1][h][nb][64] : &g_Ke[1][h][nb][64];
        ((uint4*)xh)[0] = ((const uint4*)ehw)[0]; ((uint4*)xh)[1] = ((const uint4*)ehw)[1];
        ((uint4*)xl)[0] = ((const uint4*)elw)[0]; ((uint4*)xl)[1] = ((const uint4*)elw)[1];
    }
}

// ---------------------------------------------------------------------------
// Kernel 2: HMMA flash attention, split-K (NSPLIT), 32 query rows per warp.
// grid (NN/QT, H, NSPLIT), 128 threads.
// ---------------------------------------------------------------------------
__global__ __launch_bounds__(128)
void attn_kernel()
{
    extern __shared__ __align__(16) uint8_t smem[];

    const int tid  = threadIdx.x;
    const int wid  = tid >> 5;
    const int lane = tid & 31;
    const int h    = blockIdx.y;
    const int s    = blockIdx.z;
    const int q0   = blockIdx.x * QT;

    const uint32_t sbase = smem_u32(smem);

    // ---- stage full Q tile (128 rows, hi/lo) across both stage buffers ----
    for (int u = tid; u < 128 * 10; u += 128) {
        int row = u / 10, w = u - row * 10;
        uint32_t off = row * KSTRIDE + w * 16;
        *(uint4*)(smem + off)         = ((const uint4*)&g_Qe[0][h][q0 + row][0])[w];
        *(uint4*)(smem + 22528 + off) = ((const uint4*)&g_Qe[1][h][q0 + row][0])[w];
    }
    __syncthreads();

    uint32_t qh[2][5][4], ql[2][5][4];
#pragma unroll
    for (int r = 0; r < 2; r++) {
        uint32_t qoff = (wid * 32 + r * 16 + (lane & 15)) * KSTRIDE + (lane >> 4) * 16;
#pragma unroll
        for (int ks = 0; ks < 5; ks++) {
            ldm_x4(qh[r][ks], sbase + qoff + ks * 32);
            ldm_x4(ql[r][ks], sbase + 22528 + qoff + ks * 32);
        }
    }
    __syncthreads();

    const int hl = (lane >> 4) & 1;
    uint32_t kb[2], vb[2];
#pragma unroll
    for (int st = 0; st < 2; st++) {
        kb[st] = sbase + st * STAGE_BYTES + (hl ? KB_HL : 0)
               + (lane & 7) * KSTRIDE + ((lane >> 3) & 1) * 16;
        vb[st] = sbase + st * STAGE_BYTES + 2 * KB_HL + (hl ? VB_HL : 0)
               + (lane & 7) * VSTRIDE + ((lane >> 3) & 1) * 16;
    }

    auto prefetch = [&](int tt, int st) {
        const int j0 = tt * KT;
        const uint32_t kB = sbase + st * STAGE_BYTES;
        for (int u = tid; u < 64 * 10; u += 128) {
            int row = u / 10, w = u - row * 10;
            uint32_t off = kB + row * KSTRIDE + w * 16;
            cp16(off,          &g_Ke[0][h][j0 + row][w * 8]);
            cp16(off + KB_HL,  &g_Ke[1][h][j0 + row][w * 8]);
        }
        const uint32_t vB = kB + 2 * KB_HL;
        for (int u = tid; u < 64 * 8; u += 128) {
            int row = u >> 3, w = u & 7;
            uint32_t off = vB + row * VSTRIDE + w * 16;
            cp16(off,          &g_Vt[0][h][row][j0 + w * 8]);
            cp16(off + VB_HL,  &g_Vt[1][h][row][j0 + w * 8]);
        }
    };

    float m[2][2], l[2][2];
#pragma unroll
    for (int r = 0; r < 2; r++) { m[r][0] = m[r][1] = -INFINITY; l[r][0] = l[r][1] = 0.f; }
    float o[2][8][4];
#pragma unroll
    for (int r = 0; r < 2; r++)
#pragma unroll
        for (int g = 0; g < 8; g++) { o[r][g][0]=0.f; o[r][g][1]=0.f; o[r][g][2]=0.f; o[r][g][3]=0.f; }

    prefetch(s * NT2, 0);
    CP_COMMIT();

    for (int t = 0; t < NT2; t++) {
        const int cur = t & 1;
        if (t + 1 < NT2) {
            prefetch(s * NT2 + t + 1, cur ^ 1);
            CP_COMMIT();
            CP_WAIT1();
        } else {
            CP_WAIT0();
        }
        __syncthreads();

        // ---- S = Qext @ Kext^T : 2 rowsets x 3 split terms ----
        float c[2][8][4];
#pragma unroll
        for (int r = 0; r < 2; r++)
#pragma unroll
            for (int g = 0; g < 8; g++) { c[r][g][0]=0.f; c[r][g][1]=0.f; c[r][g][2]=0.f; c[r][g][3]=0.f; }
#pragma unroll
        for (int g = 0; g < 8; g++) {
            uint32_t base = kb[cur] + g * 8 * KSTRIDE;
#pragma unroll
            for (int ks = 0; ks < 5; ks++) {
                uint32_t b[4];
                ldm_x4(b, base + ks * 32);
#pragma unroll
                for (int r = 0; r < 2; r++) {
                    mma16816(c[r][g], qh[r][ks], b[0], b[1]);
                    mma16816(c[r][g], ql[r][ks], b[0], b[1]);
                    mma16816(c[r][g], qh[r][ks], b[2], b[3]);
                }
            }
        }

        // ---- online softmax per rowset ----
        bool upd = false;
        float mn[2][2];
#pragma unroll
        for (int r = 0; r < 2; r++) {
            float r0 = -INFINITY, r1 = -INFINITY;
#pragma unroll
            for (int g = 0; g < 8; g++) {
                r0 = fmaxf(r0, fmaxf(c[r][g][0], c[r][g][1]));
                r1 = fmaxf(r1, fmaxf(c[r][g][2], c[r][g][3]));
            }
            r0 = fmaxf(r0, __shfl_xor_sync(0xffffffffu, r0, 1));
            r0 = fmaxf(r0, __shfl_xor_sync(0xffffffffu, r0, 2));
            r1 = fmaxf(r1, __shfl_xor_sync(0xffffffffu, r1, 1));
            r1 = fmaxf(r1, __shfl_xor_sync(0xffffffffu, r1, 2));
            mn[r][0] = fmaxf(m[r][0], r0);
            mn[r][1] = fmaxf(m[r][1], r1);
            upd |= (mn[r][0] > m[r][0]) | (mn[r][1] > m[r][1]);
        }
        if (__any_sync(0xffffffffu, upd)) {
#pragma unroll
            for (int r = 0; r < 2; r++) {
                float sc0 = ex2(m[r][0] - mn[r][0]);
                float sc1 = ex2(m[r][1] - mn[r][1]);
                l[r][0] *= sc0; l[r][1] *= sc1;
#pragma unroll
                for (int g = 0; g < 8; g++) {
                    o[r][g][0] *= sc0; o[r][g][1] *= sc0;
                    o[r][g][2] *= sc1; o[r][g][3] *= sc1;
                }
            }
        }
#pragma unroll
        for (int r = 0; r < 2; r++) { m[r][0] = mn[r][0]; m[r][1] = mn[r][1]; }

        uint32_t ph[2][4][4], pl[2][4][4];
#pragma unroll
        for (int r = 0; r < 2; r++) {
            float ls0 = 0.f, ls1 = 0.f;
#pragma unroll
            for (int g = 0; g < 8; g++) {
                c[r][g][0] = ex2(c[r][g][0] - m[r][0]);
                c[r][g][1] = ex2(c[r][g][1] - m[r][0]);
                c[r][g][2] = ex2(c[r][g][2] - m[r][1]);
                c[r][g][3] = ex2(c[r][g][3] - m[r][1]);
                ls0 += c[r][g][0] + c[r][g][1];
                ls1 += c[r][g][2] + c[r][g][3];
            }
            l[r][0] += ls0;
            l[r][1] += ls1;
#pragma unroll
            for (int kk = 0; kk < 4; kk++) {
                pack_hilo(c[r][2*kk][0],   c[r][2*kk][1],   ph[r][kk][0], pl[r][kk][0]);
                pack_hilo(c[r][2*kk][2],   c[r][2*kk][3],   ph[r][kk][1], pl[r][kk][1]);
                pack_hilo(c[r][2*kk+1][0], c[r][2*kk+1][1], ph[r][kk][2], pl[r][kk][2]);
                pack_hilo(c[r][2*kk+1][2], c[r][2*kk+1][3], ph[r][kk][3], pl[r][kk][3]);
            }
        }

        // ---- O += P @ V^T : 3 terms (Phi*Vhi, Plo*Vhi, Phi*Vlo) ----
#pragma unroll
        for (int g = 0; g < 8; g++) {
            uint32_t base = vb[cur] + g * 8 * VSTRIDE;
#pragma unroll
            for (int kk = 0; kk < 4; kk++) {
                uint32_t v[4];
                ldm_x4(v, base + kk * 32);
#pragma unroll
                for (int r = 0; r < 2; r++) {
                    mma16816(o[r][g], ph[r][kk], v[0], v[1]);
                    mma16816(o[r][g], pl[r][kk], v[0], v[1]);
                    mma16816(o[r][g], ph[r][kk], v[2], v[3]);
                }
            }
        }
        __syncthreads();
    }

    // ---- epilogue: write split partials ----
#pragma unroll
    for (int r = 0; r < 2; r++) {
        l[r][0] += __shfl_xor_sync(0xffffffffu, l[r][0], 1);
        l[r][0] += __shfl_xor_sync(0xffffffffu, l[r][0], 2);
        l[r][1] += __shfl_xor_sync(0xffffffffu, l[r][1], 1);
        l[r][1] += __shfl_xor_sync(0xffffffffu, l[r][1], 2);

        const int r0row = q0 + wid * 32 + r * 16 + (lane >> 2);
        const int r1row = r0row + 8;
        if ((lane & 3) == 0) {
            g_pm[(s * H + h) * NN + r0row] = m[r][0];
            g_pm[(s * H + h) * NN + r1row] = m[r][1];
            g_pl[(s * H + h) * NN + r0row] = l[r][0];
            g_pl[(s * H + h) * NN + r1row] = l[r][1];
        }
        const int dcol = 2 * (lane & 3);
#pragma unroll
        for (int g = 0; g < 8; g++) {
            int d = 8 * g + dcol;
            *reinterpret_cast<float2*>(&g_pO[s][h][r0row][d]) = make_float2(o[r][g][0], o[r][g][1]);
            *reinterpret_cast<float2*>(&g_pO[s][h][r1row][d]) = make_float2(o[r][g][2], o[r][g][3]);
        }
    }
}

// ---------------------------------------------------------------------------
// Kernel 2b: combine split partials -> g_O. thread per (h,n).
// ---------------------------------------------------------------------------
__global__ __launch_bounds__(128)
void combine_kernel()
{
    const int gid = blockIdx.x * 128 + threadIdx.x;   // h*NN + n
    const int HN = H * NN;
    const int hh = gid / NN, n = gid - hh * NN;

    float m0 = g_pm[gid], m1 = g_pm[HN + gid];
    float M = fmaxf(m0, m1);
    float w0 = ex2(m0 - M), w1 = ex2(m1 - M);
    float l = w0 * g_pl[gid] + w1 * g_pl[HN + gid];
    float inv = 1.0f / (l * 64.0f);   // 64 = sqrt(4096)
    w0 *= inv; w1 *= inv;

    const float4* a0 = (const float4*)&g_pO[0][hh][n][0];
    const float4* a1 = (const float4*)&g_pO[1][hh][n][0];
    float4* Op = (float4*)&g_O[hh][n][0];
#pragma unroll
    for (int t = 0; t < 16; t++) {
        float4 x0 = a0[t], x1 = a1[t];
        Op[t] = make_float4(w0*x0.x + w1*x1.x, w0*x0.y + w1*x1.y,
                            w0*x0.z + w1*x1.z, w0*x0.w + w1*x1.w);
    }
}

// ---------------------------------------------------------------------------
// Kernel 3: output projection, thread per output element.
// ---------------------------------------------------------------------------
#define A_ELEMS (NN * ADIM)
#define O_ELEMS (A_ELEMS + NN * VDIM * 3)

__global__ __launch_bounds__(256)
void out_kernel(const float* __restrict__ W_ao, const float* __restrict__ W_vo,
                float* __restrict__ out)
{
    __shared__ float s_ao[H * ADIM * CHAN];
    __shared__ float s_vo[H * VDIM * CHAN];
    for (int t = threadIdx.x; t < H * ADIM * CHAN; t += 256) s_ao[t] = W_ao[t];
    for (int t = threadIdx.x; t < H * VDIM * CHAN; t += 256) s_vo[t] = W_vo[t];
    __syncthreads();

    const int gid = blockIdx.x * 256 + threadIdx.x;
    if (gid < A_ELEMS) {
        const int n = gid >> 6, j = gid & 63;
        float acc = 0.f;
#pragma unroll
        for (int h = 0; h < H; h++) {
            const float* O = &g_O[h][n][0];
            const float* w = s_ao + h * ADIM * CHAN + j * CHAN;
#pragma unroll
            for (int i = 0; i < CHAN; i++) acc += w[i] * O[i];
        }
        out[gid] = acc;
    } else {
        const int idx = gid - A_ELEMS;
        const int n = idx / 48, jv = idx - n * 48;
        const int j = jv / 3, vv = jv - j * 3;
        float acc = 0.f;
#pragma unroll
        for (int h = 0; h < H; h++) {
            const float* O = &g_O[h][n][CHAN + vv];
            const float* w = s_vo + h * VDIM * CHAN + j * CHAN;
#pragma unroll
            for (int c = 0; c < CHAN; c++) acc += w[c] * O[3 * c];
        }
        out[gid] = acc;
    }
}

// ---------------------------------------------------------------------------
extern "C" void kernel_launch(void* const* d_in, const int* in_sizes, int n_in,
                              void* d_out, int out_size)
{
    const float* ax    = (const float*)d_in[0];
    const float* vx    = (const float*)d_in[1];
    const float* pos_k = (const float*)d_in[2];
    const float* pos_q = (const float*)d_in[3];
    const float* W_aq  = (const float*)d_in[4];
    const float* W_vq  = (const float*)d_in[5];
    const float* W_ak  = (const float*)d_in[6];
    const float* W_vk  = (const float*)d_in[7];
    const float* W_av  = (const float*)d_in[8];
    const float* W_vv  = (const float*)d_in[9];
    const float* W_ao  = (const float*)d_in[10];
    const float* W_vo  = (const float*)d_in[11];
    float* out = (float*)d_out;

    cudaFuncSetAttribute(attn_kernel, cudaFuncAttributeMaxDynamicSharedMemorySize,
                         SMEM_BYTES);

    proj_kernel<<<dim3(NN / 64, H, 3), 256>>>(ax, vx, pos_q, pos_k,
                                              W_aq, W_vq, W_ak, W_vk, W_av, W_vv);
    attn_kernel<<<dim3(NN / QT, H, NSPLIT), 128, SMEM_BYTES>>>();
    combine_kernel<<<H * NN / 128, 128>>>();
    out_kernel<<<(O_ELEMS + 255) / 256, 256>>>(W_ao, W_vo, out);
}